// round 2
// baseline (speedup 1.0000x reference)
#include <cuda_runtime.h>
#include <cuda_bf16.h>
#include <math.h>

// ----------------------------------------------------------------------------
// Problem constants: B=2, T=2048, C=1024, H=16, D=64, 3C=3072, 4C=4096
// Tokens M = B*T = 4096.
// ----------------------------------------------------------------------------
#define M_TOK   4096
#define C_DIM   1024
#define C3_DIM  3072
#define C4_DIM  4096
#define N_HEAD  16
#define HDIM    64
#define T_SEQ   2048

// Scratch (device globals: allowed; zero-init BSS, no runtime allocation)
__device__ float g_h  [M_TOK * C_DIM];    // LN output (reused for LN1 and LN2)
__device__ float g_qkv[M_TOK * C3_DIM];   // QKV
__device__ float g_y  [M_TOK * C_DIM];    // attention output
__device__ float g_x1 [M_TOK * C_DIM];    // residual-1 output
__device__ float g_fc [M_TOK * C4_DIM];   // FC (post-GELU)

// ----------------------------------------------------------------------------
// LayerNorm: one block per token row (1024 elements), 256 threads x 4 floats
// ----------------------------------------------------------------------------
__global__ void __launch_bounds__(256) ln_kernel(
    const float* __restrict__ x, const float* __restrict__ g,
    const float* __restrict__ b, float* __restrict__ out)
{
    __shared__ float red_s[8], red_ss[8];
    const int row = blockIdx.x;
    const int t = threadIdx.x;
    const float* xr = x + (size_t)row * C_DIM;

    float4 v = *(const float4*)(xr + t * 4);
    float s  = v.x + v.y + v.z + v.w;
    float ss = v.x*v.x + v.y*v.y + v.z*v.z + v.w*v.w;
    #pragma unroll
    for (int o = 16; o; o >>= 1) {
        s  += __shfl_xor_sync(0xffffffffu, s,  o);
        ss += __shfl_xor_sync(0xffffffffu, ss, o);
    }
    if ((t & 31) == 0) { red_s[t >> 5] = s; red_ss[t >> 5] = ss; }
    __syncthreads();
    if (t < 32) {
        float a = (t < 8) ? red_s[t]  : 0.f;
        float c = (t < 8) ? red_ss[t] : 0.f;
        #pragma unroll
        for (int o = 4; o; o >>= 1) {
            a += __shfl_xor_sync(0xffffffffu, a, o);
            c += __shfl_xor_sync(0xffffffffu, c, o);
        }
        if (t == 0) { red_s[0] = a; red_ss[0] = c; }
    }
    __syncthreads();
    const float mu  = red_s[0]  * (1.0f / C_DIM);
    const float var = red_ss[0] * (1.0f / C_DIM) - mu * mu;
    const float inv = rsqrtf(var + 1e-5f);

    float4 gv = *(const float4*)(g + t * 4);
    float4 bv = *(const float4*)(b + t * 4);
    float4 o;
    o.x = (v.x - mu) * inv * gv.x + bv.x;
    o.y = (v.y - mu) * inv * gv.y + bv.y;
    o.z = (v.z - mu) * inv * gv.z + bv.z;
    o.w = (v.w - mu) * inv * gv.w + bv.w;
    *(float4*)(out + (size_t)row * C_DIM + t * 4) = o;
}

// ----------------------------------------------------------------------------
// Tiled SGEMM: C = A[M,K] @ W[K,N] + bias, with epilogue modes
//   MODE 0: + bias
//   MODE 1: + bias + residual
//   MODE 2: gelu_tanh(+ bias)
// Tile 128x128x8, 256 threads, 8x8 per thread. All dims divisible by 128/8.
// ----------------------------------------------------------------------------
__device__ __forceinline__ float gelu_t(float x) {
    float x3 = x * x * x;
    float u = 0.7978845608028654f * (x + 0.044715f * x3);
    return 0.5f * x * (1.0f + tanhf(u));
}

template <int MODE>
__global__ void __launch_bounds__(256) sgemm_kernel(
    const float* __restrict__ A, const float* __restrict__ W,
    const float* __restrict__ bias, const float* __restrict__ res,
    float* __restrict__ C, int M, int N, int K)
{
    __shared__ float As[8][128];
    __shared__ float Bs[8][128];

    const int t   = threadIdx.x;
    const int bm0 = blockIdx.y * 128;
    const int bn0 = blockIdx.x * 128;

    const int arow = t >> 1, aseg = (t & 1) << 2;
    const int brow = t >> 5, bcol = (t & 31) << 2;
    const float* Ap = A + (size_t)(bm0 + arow) * K + aseg;
    const float* Wp = W + (size_t)brow * N + bn0 + bcol;

    const int ty = t >> 4, tx = t & 15;

    float acc[8][8];
    #pragma unroll
    for (int i = 0; i < 8; i++)
        #pragma unroll
        for (int j = 0; j < 8; j++) acc[i][j] = 0.f;

    for (int k0 = 0; k0 < K; k0 += 8) {
        float4 a4 = *(const float4*)(Ap + k0);
        float4 b4 = *(const float4*)(Wp + (size_t)k0 * N);
        __syncthreads();
        As[aseg + 0][arow] = a4.x;
        As[aseg + 1][arow] = a4.y;
        As[aseg + 2][arow] = a4.z;
        As[aseg + 3][arow] = a4.w;
        *(float4*)&Bs[brow][bcol] = b4;
        __syncthreads();

        #pragma unroll
        for (int kk = 0; kk < 8; kk++) {
            float4 a0 = *(float4*)&As[kk][ty * 8];
            float4 a1 = *(float4*)&As[kk][ty * 8 + 4];
            float4 b0 = *(float4*)&Bs[kk][tx * 8];
            float4 b1 = *(float4*)&Bs[kk][tx * 8 + 4];
            float ar[8] = {a0.x, a0.y, a0.z, a0.w, a1.x, a1.y, a1.z, a1.w};
            float br[8] = {b0.x, b0.y, b0.z, b0.w, b1.x, b1.y, b1.z, b1.w};
            #pragma unroll
            for (int i = 0; i < 8; i++)
                #pragma unroll
                for (int j = 0; j < 8; j++)
                    acc[i][j] += ar[i] * br[j];
        }
    }

    // Epilogue
    #pragma unroll
    for (int i = 0; i < 8; i++) {
        const int row = bm0 + ty * 8 + i;
        float* crow = C + (size_t)row * N + bn0 + tx * 8;
        const float* rrow = (MODE == 1) ? (res + (size_t)row * N + bn0 + tx * 8) : nullptr;
        #pragma unroll
        for (int j0 = 0; j0 < 8; j0 += 4) {
            float vv[4];
            #pragma unroll
            for (int jj = 0; jj < 4; jj++) {
                float v = acc[i][j0 + jj] + bias[bn0 + tx * 8 + j0 + jj];
                if (MODE == 1) v += rrow[j0 + jj];
                if (MODE == 2) v = gelu_t(v);
                vv[jj] = v;
            }
            float4 o = {vv[0], vv[1], vv[2], vv[3]};
            *(float4*)(crow + j0) = o;
        }
    }
}

// ----------------------------------------------------------------------------
// Causal attention, flash-style online softmax.
// Grid: (T/64, H, B). Block: 256 threads. Q-tile 64 rows; KV tiles of 64.
// Thread t: owns S row r=t>>2; S cols interleaved c=q4+4*j (conflict-free);
// O dims contiguous d = q4*16 + i.
// ----------------------------------------------------------------------------
#define AT_STRIDE 68
#define AT_SMEM   (4 * 64 * AT_STRIDE * (int)sizeof(float))
#define BIGNEG    (-1e30f)

__global__ void __launch_bounds__(256) attn_kernel(
    const float* __restrict__ qkv, float* __restrict__ y)
{
    extern __shared__ float sm[];
    float* Qs = sm;
    float* Ks = Qs + 64 * AT_STRIDE;
    float* Vs = Ks + 64 * AT_STRIDE;
    float* Ss = Vs + 64 * AT_STRIDE;

    const int qt = blockIdx.x, h = blockIdx.y, b = blockIdx.z;
    const int t = threadIdx.x;
    const float* base = qkv + (size_t)b * T_SEQ * C3_DIM + h * HDIM;

    // Load Q tile [64 x 64]
    #pragma unroll
    for (int i = 0; i < 4; i++) {
        int id = t + 256 * i;             // 1024 float4s
        int row = id >> 4, c4 = (id & 15) << 2;
        float4 v = *(const float4*)(base + (size_t)(qt * 64 + row) * C3_DIM + c4);
        *(float4*)&Qs[row * AT_STRIDE + c4] = v;
    }

    const int r = t >> 2, q4 = t & 3;
    const int qrow = qt * 64 + r;
    float m = BIGNEG, l = 0.f;
    float O[16];
    #pragma unroll
    for (int i = 0; i < 16; i++) O[i] = 0.f;

    for (int j = 0; j <= qt; j++) {
        __syncthreads();   // previous iter done with Ks/Vs/Ss (also orders Q load at j=0 w/ 2nd sync)
        #pragma unroll
        for (int i = 0; i < 4; i++) {
            int id = t + 256 * i;
            int row = id >> 4, c4 = (id & 15) << 2;
            const float* kb = base + (size_t)(j * 64 + row) * C3_DIM + C_DIM + c4;
            *(float4*)&Ks[row * AT_STRIDE + c4] = *(const float4*)kb;
            *(float4*)&Vs[row * AT_STRIDE + c4] = *(const float4*)(kb + C_DIM);
        }
        __syncthreads();

        // S = (Q K^T) * 1/sqrt(64), causal mask on diagonal tile
        float s[16];
        #pragma unroll
        for (int jj = 0; jj < 16; jj++) s[jj] = 0.f;
        #pragma unroll 4
        for (int k = 0; k < 64; k += 4) {
            float4 qv = *(float4*)&Qs[r * AT_STRIDE + k];
            #pragma unroll
            for (int jj = 0; jj < 16; jj++) {
                int c = q4 + 4 * jj;
                float4 kv = *(float4*)&Ks[c * AT_STRIDE + k];
                s[jj] += qv.x * kv.x + qv.y * kv.y + qv.z * kv.z + qv.w * kv.w;
            }
        }

        float mt = BIGNEG;
        #pragma unroll
        for (int jj = 0; jj < 16; jj++) {
            int c = q4 + 4 * jj;
            float sv = s[jj] * 0.125f;
            if (j == qt && (j * 64 + c) > qrow) sv = BIGNEG;
            s[jj] = sv;
            mt = fmaxf(mt, sv);
        }
        mt = fmaxf(mt, __shfl_xor_sync(0xffffffffu, mt, 1));
        mt = fmaxf(mt, __shfl_xor_sync(0xffffffffu, mt, 2));
        float mnew = fmaxf(m, mt);
        float alpha = __expf(m - mnew);

        float psum = 0.f;
        #pragma unroll
        for (int jj = 0; jj < 16; jj++) {
            float p = __expf(s[jj] - mnew);
            psum += p;
            Ss[r * AT_STRIDE + q4 + 4 * jj] = p;
        }
        psum += __shfl_xor_sync(0xffffffffu, psum, 1);
        psum += __shfl_xor_sync(0xffffffffu, psum, 2);
        l = l * alpha + psum;
        m = mnew;
        #pragma unroll
        for (int i = 0; i < 16; i++) O[i] *= alpha;
        __syncthreads();

        // O += P @ V (thread owns dims d = q4*16 .. q4*16+15)
        #pragma unroll 4
        for (int c = 0; c < 64; c++) {
            float p = Ss[r * AT_STRIDE + c];
            const float* vrow = &Vs[c * AT_STRIDE + q4 * 16];
            float4 v0 = *(const float4*)(vrow + 0);
            float4 v1 = *(const float4*)(vrow + 4);
            float4 v2 = *(const float4*)(vrow + 8);
            float4 v3 = *(const float4*)(vrow + 12);
            O[0]  += p * v0.x; O[1]  += p * v0.y; O[2]  += p * v0.z; O[3]  += p * v0.w;
            O[4]  += p * v1.x; O[5]  += p * v1.y; O[6]  += p * v1.z; O[7]  += p * v1.w;
            O[8]  += p * v2.x; O[9]  += p * v2.y; O[10] += p * v2.z; O[11] += p * v2.w;
            O[12] += p * v3.x; O[13] += p * v3.y; O[14] += p * v3.z; O[15] += p * v3.w;
        }
    }

    const float invl = 1.0f / l;
    float* yout = y + (size_t)(b * T_SEQ + qrow) * C_DIM + h * HDIM + q4 * 16;
    #pragma unroll
    for (int i = 0; i < 16; i += 4) {
        float4 o = {O[i] * invl, O[i + 1] * invl, O[i + 2] * invl, O[i + 3] * invl};
        *(float4*)(yout + i) = o;
    }
}

// ----------------------------------------------------------------------------
// Launch
// ----------------------------------------------------------------------------
extern "C" void kernel_launch(void* const* d_in, const int* in_sizes, int n_in,
                              void* d_out, int out_size)
{
    const float* x      = (const float*)d_in[0];
    const float* ln1_g  = (const float*)d_in[1];
    const float* ln1_b  = (const float*)d_in[2];
    const float* W_attn = (const float*)d_in[3];
    const float* b_attn = (const float*)d_in[4];
    const float* W_o    = (const float*)d_in[5];
    const float* b_o    = (const float*)d_in[6];
    const float* ln2_g  = (const float*)d_in[7];
    const float* ln2_b  = (const float*)d_in[8];
    const float* W_fc   = (const float*)d_in[9];
    const float* b_fc   = (const float*)d_in[10];
    const float* W_fc2  = (const float*)d_in[11];
    const float* b_fc2  = (const float*)d_in[12];
    float* out = (float*)d_out;

    float *h, *qkv, *y, *x1, *fc;
    cudaGetSymbolAddress((void**)&h,   g_h);
    cudaGetSymbolAddress((void**)&qkv, g_qkv);
    cudaGetSymbolAddress((void**)&y,   g_y);
    cudaGetSymbolAddress((void**)&x1,  g_x1);
    cudaGetSymbolAddress((void**)&fc,  g_fc);

    cudaFuncSetAttribute(attn_kernel, cudaFuncAttributeMaxDynamicSharedMemorySize, AT_SMEM);

    // 1) LN1
    ln_kernel<<<M_TOK, 256>>>(x, ln1_g, ln1_b, h);
    // 2) QKV = h @ W_attn + b_attn   [4096 x 3072]
    sgemm_kernel<0><<<dim3(C3_DIM / 128, M_TOK / 128), 256>>>(
        h, W_attn, b_attn, nullptr, qkv, M_TOK, C3_DIM, C_DIM);
    // 3) causal attention -> y
    attn_kernel<<<dim3(T_SEQ / 64, N_HEAD, 2), 256, AT_SMEM>>>(qkv, y);
    // 4) x1 = x + y @ W_o + b_o
    sgemm_kernel<1><<<dim3(C_DIM / 128, M_TOK / 128), 256>>>(
        y, W_o, b_o, x, x1, M_TOK, C_DIM, C_DIM);
    // 5) LN2
    ln_kernel<<<M_TOK, 256>>>(x1, ln2_g, ln2_b, h);
    // 6) fc = gelu(h @ W_fc + b_fc)  [4096 x 4096]
    sgemm_kernel<2><<<dim3(C4_DIM / 128, M_TOK / 128), 256>>>(
        h, W_fc, b_fc, nullptr, fc, M_TOK, C4_DIM, C_DIM);
    // 7) out = x1 + fc @ W_fc2 + b_fc2
    sgemm_kernel<1><<<dim3(C_DIM / 128, M_TOK / 128), 256>>>(
        fc, W_fc2, b_fc2, x1, out, M_TOK, C_DIM, C4_DIM);
}

// round 4
// speedup vs baseline: 1.5944x; 1.5944x over previous
#include <cuda_runtime.h>
#include <cuda_bf16.h>
#include <math.h>
#include <stdint.h>

typedef __nv_bfloat16 bf16;

#define M_TOK   4096
#define C_DIM   1024
#define C3_DIM  3072
#define C4_DIM  4096
#define N_HEAD  16
#define HDIM    64
#define T_SEQ   2048

// ---------------------------------------------------------------------------
// Scratch (device globals; no runtime allocation)
// ---------------------------------------------------------------------------
__device__ bf16  g_h_hi [M_TOK * C_DIM];
__device__ bf16  g_h_lo [M_TOK * C_DIM];
__device__ float g_qkv  [M_TOK * C3_DIM];
__device__ bf16  g_y_hi [M_TOK * C_DIM];
__device__ bf16  g_y_lo [M_TOK * C_DIM];
__device__ float g_x1   [M_TOK * C_DIM];
__device__ bf16  g_fc_hi[M_TOK * C4_DIM];
__device__ bf16  g_fc_lo[M_TOK * C4_DIM];
// Transposed + hi/lo-split weights: [N, K] K-major
__device__ bf16  g_Wa_hi[C3_DIM * C_DIM];
__device__ bf16  g_Wa_lo[C3_DIM * C_DIM];
__device__ bf16  g_Wo_hi[C_DIM * C_DIM];
__device__ bf16  g_Wo_lo[C_DIM * C_DIM];
__device__ bf16  g_Wf_hi[C4_DIM * C_DIM];
__device__ bf16  g_Wf_lo[C4_DIM * C_DIM];
__device__ bf16  g_W2_hi[C_DIM * C4_DIM];
__device__ bf16  g_W2_lo[C_DIM * C4_DIM];

// ---------------------------------------------------------------------------
// Helpers
// ---------------------------------------------------------------------------
__device__ __forceinline__ uint32_t sm_u32(const void* p) {
    uint32_t a;
    asm("{ .reg .u64 t; cvta.to.shared.u64 t, %1; cvt.u32.u64 %0, t; }"
        : "=r"(a) : "l"(p));
    return a;
}

__device__ __forceinline__ void cp16(uint32_t s, const void* g) {
    asm volatile("cp.async.cg.shared.global [%0], [%1], 16;"
                 :: "r"(s), "l"(g) : "memory");
}
#define CP_COMMIT() asm volatile("cp.async.commit_group;" ::: "memory")
#define CP_WAIT1()  asm volatile("cp.async.wait_group 1;" ::: "memory")

__device__ __forceinline__ void ldsm4(uint32_t* r, uint32_t a) {
    asm volatile("ldmatrix.sync.aligned.m8n8.x4.shared.b16 {%0,%1,%2,%3}, [%4];"
        : "=r"(r[0]), "=r"(r[1]), "=r"(r[2]), "=r"(r[3]) : "r"(a));
}

__device__ __forceinline__ void mma16816(float* d, const uint32_t* a,
                                         uint32_t b0, uint32_t b1) {
    asm volatile("mma.sync.aligned.m16n8k16.row.col.f32.bf16.bf16.f32 "
        "{%0,%1,%2,%3}, {%4,%5,%6,%7}, {%8,%9}, {%0,%1,%2,%3};"
        : "+f"(d[0]), "+f"(d[1]), "+f"(d[2]), "+f"(d[3])
        : "r"(a[0]), "r"(a[1]), "r"(a[2]), "r"(a[3]), "r"(b0), "r"(b1));
}

__device__ __forceinline__ float gelu_t(float x) {
    float x3 = x * x * x;
    float u = 0.7978845608028654f * (x + 0.044715f * x3);
    return 0.5f * x * (1.0f + tanhf(u));
}

__device__ __forceinline__ void split_bf16(float v, bf16& hi, bf16& lo) {
    hi = __float2bfloat16(v);
    lo = __float2bfloat16(v - __bfloat162float(hi));
}

// ---------------------------------------------------------------------------
// Weight transpose + hi/lo split: W[K,N] fp32 -> Th[N,K], Tl[N,K] bf16
// ---------------------------------------------------------------------------
__global__ void __launch_bounds__(256) wconv_kernel(
    const float* __restrict__ W, bf16* __restrict__ Th, bf16* __restrict__ Tl,
    int K, int N)
{
    __shared__ float tile[32][33];
    const int n0 = blockIdx.x * 32, k0 = blockIdx.y * 32;
    const int tx = threadIdx.x & 31, ty = threadIdx.x >> 5;   // 32 x 8
    #pragma unroll
    for (int j = 0; j < 32; j += 8)
        tile[ty + j][tx] = W[(size_t)(k0 + ty + j) * N + n0 + tx];
    __syncthreads();
    #pragma unroll
    for (int j = 0; j < 32; j += 8) {
        float v = tile[tx][ty + j];
        bf16 hi, lo; split_bf16(v, hi, lo);
        size_t idx = (size_t)(n0 + ty + j) * K + k0 + tx;
        Th[idx] = hi; Tl[idx] = lo;
    }
}

// ---------------------------------------------------------------------------
// LayerNorm -> bf16 hi/lo output
// ---------------------------------------------------------------------------
__global__ void __launch_bounds__(256) ln_kernel(
    const float* __restrict__ x, const float* __restrict__ g,
    const float* __restrict__ b, bf16* __restrict__ oh, bf16* __restrict__ ol)
{
    __shared__ float red_s[8], red_ss[8];
    const int row = blockIdx.x;
    const int t = threadIdx.x;
    const float* xr = x + (size_t)row * C_DIM;

    float4 v = *(const float4*)(xr + t * 4);
    float s  = v.x + v.y + v.z + v.w;
    float ss = v.x*v.x + v.y*v.y + v.z*v.z + v.w*v.w;
    #pragma unroll
    for (int o = 16; o; o >>= 1) {
        s  += __shfl_xor_sync(0xffffffffu, s,  o);
        ss += __shfl_xor_sync(0xffffffffu, ss, o);
    }
    if ((t & 31) == 0) { red_s[t >> 5] = s; red_ss[t >> 5] = ss; }
    __syncthreads();
    if (t < 32) {
        float a = (t < 8) ? red_s[t]  : 0.f;
        float c = (t < 8) ? red_ss[t] : 0.f;
        #pragma unroll
        for (int o = 4; o; o >>= 1) {
            a += __shfl_xor_sync(0xffffffffu, a, o);
            c += __shfl_xor_sync(0xffffffffu, c, o);
        }
        if (t == 0) { red_s[0] = a; red_ss[0] = c; }
    }
    __syncthreads();
    const float mu  = red_s[0]  * (1.0f / C_DIM);
    const float var = red_ss[0] * (1.0f / C_DIM) - mu * mu;
    const float inv = rsqrtf(var + 1e-5f);

    float4 gv = *(const float4*)(g + t * 4);
    float4 bv = *(const float4*)(b + t * 4);
    float o0 = (v.x - mu) * inv * gv.x + bv.x;
    float o1 = (v.y - mu) * inv * gv.y + bv.y;
    float o2 = (v.z - mu) * inv * gv.z + bv.z;
    float o3 = (v.w - mu) * inv * gv.w + bv.w;

    bf16 h0,l0,h1,l1,h2,l2,h3,l3;
    split_bf16(o0,h0,l0); split_bf16(o1,h1,l1);
    split_bf16(o2,h2,l2); split_bf16(o3,h3,l3);
    size_t base = (size_t)row * C_DIM + t * 4;
    *(__nv_bfloat162*)(oh + base)     = __nv_bfloat162(h0, h1);
    *(__nv_bfloat162*)(oh + base + 2) = __nv_bfloat162(h2, h3);
    *(__nv_bfloat162*)(ol + base)     = __nv_bfloat162(l0, l1);
    *(__nv_bfloat162*)(ol + base + 2) = __nv_bfloat162(l2, l3);
}

// ---------------------------------------------------------------------------
// mma.sync bf16x3-split GEMM: C = A @ B^T (+bias [+res] [gelu])
// A: [M,K] hi/lo bf16; B: [N,K] hi/lo bf16 (K-major).
// CTA 128x128x32, 8 warps (2x4), warp tile 64x32, cp.async double buffer.
// SMEM tile rows padded to 80B -> ldmatrix conflict-free.
// MODE 0: Cf = d + bias ; MODE 1: += res ; MODE 2: Ch/Cl = split(gelu)
// ---------------------------------------------------------------------------
#define TILE_B   10240                // 128 rows x 80 bytes
#define STAGE_B  (4 * TILE_B)         // Ah, Al, Bh, Bl
#define GM_SMEM  (2 * STAGE_B)        // 81920

template<int MODE>
__global__ void __launch_bounds__(256, 2) tc_gemm(
    const bf16* __restrict__ Ah, const bf16* __restrict__ Al,
    const bf16* __restrict__ Bh, const bf16* __restrict__ Bl,
    const float* __restrict__ bias, const float* __restrict__ res,
    float* __restrict__ Cf, bf16* __restrict__ Ch, bf16* __restrict__ Cl,
    int N, int K)
{
    extern __shared__ char smem[];
    const uint32_t sb = sm_u32(smem);
    const int t = threadIdx.x, w = t >> 5, lane = t & 31;
    const int wm = w >> 2, wn = w & 3;                 // 2 x 4 warp grid
    const int bn0 = blockIdx.x * 128, bm0 = blockIdx.y * 128;
    const int NC = K >> 5;                             // k-chunks of 32

    const char* gp[4];
    gp[0] = (const char*)(Ah + (size_t)bm0 * K);
    gp[1] = (const char*)(Al + (size_t)bm0 * K);
    gp[2] = (const char*)(Bh + (size_t)bn0 * K);
    gp[3] = (const char*)(Bl + (size_t)bn0 * K);
    const size_t ldb = (size_t)K * 2;

    // cp.async mapping: thread t -> chunk col c16 = t&3, rows r, r+64
    const int c16 = t & 3, lr = t >> 2;

    auto load_chunk = [&](int i) {
        const int k0 = i << 5;
        const uint32_t st = sb + (i & 1) * STAGE_B;
        #pragma unroll
        for (int tile = 0; tile < 4; tile++) {
            #pragma unroll
            for (int half = 0; half < 2; half++) {
                const int r = lr + half * 64;
                cp16(st + tile * TILE_B + r * 80 + c16 * 16,
                     gp[tile] + (size_t)r * ldb + (size_t)k0 * 2 + c16 * 16);
            }
        }
    };

    // ldmatrix lane offsets
    const uint32_t a_off = (uint32_t)(lane & 15) * 80 + (uint32_t)(lane >> 4) * 16;
    const uint32_t b_off = (uint32_t)((lane >> 4) * 8 + (lane & 7)) * 80
                         + (uint32_t)((lane >> 3) & 1) * 16;

    float acc[4][4][4];
    #pragma unroll
    for (int i = 0; i < 4; i++)
        #pragma unroll
        for (int j = 0; j < 4; j++)
            #pragma unroll
            for (int k = 0; k < 4; k++) acc[i][j][k] = 0.f;

    load_chunk(0); CP_COMMIT();
    load_chunk(1); CP_COMMIT();

    for (int i = 0; i < NC; i++) {
        CP_WAIT1();
        __syncthreads();

        const uint32_t st = sb + (i & 1) * STAGE_B;
        #pragma unroll
        for (int ks = 0; ks < 2; ks++) {
            const uint32_t kb = ks * 32;
            // B fragments: 2 groups of n16 (hi & lo)
            uint32_t bh[2][4], bl[2][4];
            #pragma unroll
            for (int g = 0; g < 2; g++) {
                uint32_t nb = (uint32_t)(wn * 32 + g * 16) * 80 + kb + b_off;
                ldsm4(bh[g], st + 2 * TILE_B + nb);
                ldsm4(bl[g], st + 3 * TILE_B + nb);
            }
            #pragma unroll
            for (int mi = 0; mi < 4; mi++) {
                uint32_t mb = (uint32_t)(wm * 64 + mi * 16) * 80 + kb + a_off;
                uint32_t ah[4], al[4];
                ldsm4(ah, st + mb);
                ldsm4(al, st + TILE_B + mb);
                #pragma unroll
                for (int nj = 0; nj < 4; nj++) {
                    const int g = nj >> 1, h2 = (nj & 1) * 2;
                    mma16816(acc[mi][nj], ah, bh[g][h2], bh[g][h2 + 1]);
                    mma16816(acc[mi][nj], ah, bl[g][h2], bl[g][h2 + 1]);
                    mma16816(acc[mi][nj], al, bh[g][h2], bh[g][h2 + 1]);
                }
            }
        }
        __syncthreads();
        if (i + 2 < NC) load_chunk(i + 2);
        CP_COMMIT();
    }

    // Epilogue: thread owns (r, c),(r, c+1),(r+8, c),(r+8, c+1) per tile
    const int rr = lane >> 2, cc = (lane & 3) * 2;
    #pragma unroll
    for (int mi = 0; mi < 4; mi++) {
        #pragma unroll
        for (int nj = 0; nj < 4; nj++) {
            const int r0 = bm0 + wm * 64 + mi * 16 + rr;
            const int c0 = bn0 + wn * 32 + nj * 8 + cc;
            const float2 b2 = *(const float2*)(bias + c0);
            float v00 = acc[mi][nj][0] + b2.x;
            float v01 = acc[mi][nj][1] + b2.y;
            float v10 = acc[mi][nj][2] + b2.x;
            float v11 = acc[mi][nj][3] + b2.y;
            if (MODE == 1) {
                const float2 r2a = *(const float2*)(res + (size_t)r0 * N + c0);
                const float2 r2b = *(const float2*)(res + (size_t)(r0 + 8) * N + c0);
                v00 += r2a.x; v01 += r2a.y; v10 += r2b.x; v11 += r2b.y;
            }
            if (MODE == 2) {
                v00 = gelu_t(v00); v01 = gelu_t(v01);
                v10 = gelu_t(v10); v11 = gelu_t(v11);
                bf16 h0,l0,h1,l1;
                split_bf16(v00, h0, l0); split_bf16(v01, h1, l1);
                *(__nv_bfloat162*)(Ch + (size_t)r0 * N + c0) = __nv_bfloat162(h0, h1);
                *(__nv_bfloat162*)(Cl + (size_t)r0 * N + c0) = __nv_bfloat162(l0, l1);
                split_bf16(v10, h0, l0); split_bf16(v11, h1, l1);
                *(__nv_bfloat162*)(Ch + (size_t)(r0 + 8) * N + c0) = __nv_bfloat162(h0, h1);
                *(__nv_bfloat162*)(Cl + (size_t)(r0 + 8) * N + c0) = __nv_bfloat162(l0, l1);
            } else {
                *(float2*)(Cf + (size_t)r0 * N + c0)       = make_float2(v00, v01);
                *(float2*)(Cf + (size_t)(r0 + 8) * N + c0) = make_float2(v10, v11);
            }
        }
    }
}

// ---------------------------------------------------------------------------
// Causal attention (SIMT flash) — bf16 hi/lo output
// ---------------------------------------------------------------------------
#define AT_STRIDE 68
#define AT_SMEM   (4 * 64 * AT_STRIDE * (int)sizeof(float))
#define BIGNEG    (-1e30f)

__global__ void __launch_bounds__(256) attn_kernel(
    const float* __restrict__ qkv, bf16* __restrict__ yh, bf16* __restrict__ yl)
{
    extern __shared__ float sm[];
    float* Qs = sm;
    float* Ks = Qs + 64 * AT_STRIDE;
    float* Vs = Ks + 64 * AT_STRIDE;
    float* Ss = Vs + 64 * AT_STRIDE;

    const int qt = blockIdx.x, h = blockIdx.y, b = blockIdx.z;
    const int t = threadIdx.x;
    const float* base = qkv + (size_t)b * T_SEQ * C3_DIM + h * HDIM;

    #pragma unroll
    for (int i = 0; i < 4; i++) {
        int id = t + 256 * i;
        int row = id >> 4, c4 = (id & 15) << 2;
        float4 v = *(const float4*)(base + (size_t)(qt * 64 + row) * C3_DIM + c4);
        *(float4*)&Qs[row * AT_STRIDE + c4] = v;
    }

    const int r = t >> 2, q4 = t & 3;
    const int qrow = qt * 64 + r;
    float m = BIGNEG, l = 0.f;
    float O[16];
    #pragma unroll
    for (int i = 0; i < 16; i++) O[i] = 0.f;

    for (int j = 0; j <= qt; j++) {
        __syncthreads();
        #pragma unroll
        for (int i = 0; i < 4; i++) {
            int id = t + 256 * i;
            int row = id >> 4, c4 = (id & 15) << 2;
            const float* kb = base + (size_t)(j * 64 + row) * C3_DIM + C_DIM + c4;
            *(float4*)&Ks[row * AT_STRIDE + c4] = *(const float4*)kb;
            *(float4*)&Vs[row * AT_STRIDE + c4] = *(const float4*)(kb + C_DIM);
        }
        __syncthreads();

        float s[16];
        #pragma unroll
        for (int jj = 0; jj < 16; jj++) s[jj] = 0.f;
        #pragma unroll 4
        for (int k = 0; k < 64; k += 4) {
            float4 qv = *(float4*)&Qs[r * AT_STRIDE + k];
            #pragma unroll
            for (int jj = 0; jj < 16; jj++) {
                int c = q4 + 4 * jj;
                float4 kv = *(float4*)&Ks[c * AT_STRIDE + k];
                s[jj] += qv.x * kv.x + qv.y * kv.y + qv.z * kv.z + qv.w * kv.w;
            }
        }

        float mt = BIGNEG;
        #pragma unroll
        for (int jj = 0; jj < 16; jj++) {
            int c = q4 + 4 * jj;
            float sv = s[jj] * 0.125f;
            if (j == qt && (j * 64 + c) > qrow) sv = BIGNEG;
            s[jj] = sv;
            mt = fmaxf(mt, sv);
        }
        mt = fmaxf(mt, __shfl_xor_sync(0xffffffffu, mt, 1));
        mt = fmaxf(mt, __shfl_xor_sync(0xffffffffu, mt, 2));
        float mnew = fmaxf(m, mt);
        float alpha = __expf(m - mnew);

        float psum = 0.f;
        #pragma unroll
        for (int jj = 0; jj < 16; jj++) {
            float p = __expf(s[jj] - mnew);
            psum += p;
            Ss[r * AT_STRIDE + q4 + 4 * jj] = p;
        }
        psum += __shfl_xor_sync(0xffffffffu, psum, 1);
        psum += __shfl_xor_sync(0xffffffffu, psum, 2);
        l = l * alpha + psum;
        m = mnew;
        #pragma unroll
        for (int i = 0; i < 16; i++) O[i] *= alpha;
        __syncthreads();

        #pragma unroll 4
        for (int c = 0; c < 64; c++) {
            float p = Ss[r * AT_STRIDE + c];
            const float* vrow = &Vs[c * AT_STRIDE + q4 * 16];
            float4 v0 = *(const float4*)(vrow + 0);
            float4 v1 = *(const float4*)(vrow + 4);
            float4 v2 = *(const float4*)(vrow + 8);
            float4 v3 = *(const float4*)(vrow + 12);
            O[0]  += p * v0.x; O[1]  += p * v0.y; O[2]  += p * v0.z; O[3]  += p * v0.w;
            O[4]  += p * v1.x; O[5]  += p * v1.y; O[6]  += p * v1.z; O[7]  += p * v1.w;
            O[8]  += p * v2.x; O[9]  += p * v2.y; O[10] += p * v2.z; O[11] += p * v2.w;
            O[12] += p * v3.x; O[13] += p * v3.y; O[14] += p * v3.z; O[15] += p * v3.w;
        }
    }

    const float invl = 1.0f / l;
    size_t ybase = (size_t)(b * T_SEQ + qrow) * C_DIM + h * HDIM + q4 * 16;
    #pragma unroll
    for (int i = 0; i < 16; i += 2) {
        float v0 = O[i] * invl, v1 = O[i + 1] * invl;
        bf16 h0, l0, h1, l1;
        split_bf16(v0, h0, l0); split_bf16(v1, h1, l1);
        *(__nv_bfloat162*)(yh + ybase + i) = __nv_bfloat162(h0, h1);
        *(__nv_bfloat162*)(yl + ybase + i) = __nv_bfloat162(l0, l1);
    }
}

// ---------------------------------------------------------------------------
// Launch
// ---------------------------------------------------------------------------
extern "C" void kernel_launch(void* const* d_in, const int* in_sizes, int n_in,
                              void* d_out, int out_size)
{
    const float* x      = (const float*)d_in[0];
    const float* ln1_g  = (const float*)d_in[1];
    const float* ln1_b  = (const float*)d_in[2];
    const float* W_attn = (const float*)d_in[3];
    const float* b_attn = (const float*)d_in[4];
    const float* W_o    = (const float*)d_in[5];
    const float* b_o    = (const float*)d_in[6];
    const float* ln2_g  = (const float*)d_in[7];
    const float* ln2_b  = (const float*)d_in[8];
    const float* W_fc   = (const float*)d_in[9];
    const float* b_fc   = (const float*)d_in[10];
    const float* W_fc2  = (const float*)d_in[11];
    const float* b_fc2  = (const float*)d_in[12];
    float* out = (float*)d_out;

    bf16 *h_hi, *h_lo, *y_hi, *y_lo, *fc_hi, *fc_lo;
    bf16 *Wa_hi, *Wa_lo, *Wo_hi, *Wo_lo, *Wf_hi, *Wf_lo, *W2_hi, *W2_lo;
    float *qkv, *x1;
    cudaGetSymbolAddress((void**)&h_hi,  g_h_hi);
    cudaGetSymbolAddress((void**)&h_lo,  g_h_lo);
    cudaGetSymbolAddress((void**)&qkv,   g_qkv);
    cudaGetSymbolAddress((void**)&y_hi,  g_y_hi);
    cudaGetSymbolAddress((void**)&y_lo,  g_y_lo);
    cudaGetSymbolAddress((void**)&x1,    g_x1);
    cudaGetSymbolAddress((void**)&fc_hi, g_fc_hi);
    cudaGetSymbolAddress((void**)&fc_lo, g_fc_lo);
    cudaGetSymbolAddress((void**)&Wa_hi, g_Wa_hi);
    cudaGetSymbolAddress((void**)&Wa_lo, g_Wa_lo);
    cudaGetSymbolAddress((void**)&Wo_hi, g_Wo_hi);
    cudaGetSymbolAddress((void**)&Wo_lo, g_Wo_lo);
    cudaGetSymbolAddress((void**)&Wf_hi, g_Wf_hi);
    cudaGetSymbolAddress((void**)&Wf_lo, g_Wf_lo);
    cudaGetSymbolAddress((void**)&W2_hi, g_W2_hi);
    cudaGetSymbolAddress((void**)&W2_lo, g_W2_lo);

    cudaFuncSetAttribute(attn_kernel, cudaFuncAttributeMaxDynamicSharedMemorySize, AT_SMEM);
    cudaFuncSetAttribute(tc_gemm<0>, cudaFuncAttributeMaxDynamicSharedMemorySize, GM_SMEM);
    cudaFuncSetAttribute(tc_gemm<1>, cudaFuncAttributeMaxDynamicSharedMemorySize, GM_SMEM);
    cudaFuncSetAttribute(tc_gemm<2>, cudaFuncAttributeMaxDynamicSharedMemorySize, GM_SMEM);

    // Weight prep (transpose + bf16 hi/lo split)
    wconv_kernel<<<dim3(C3_DIM / 32, C_DIM / 32), 256>>>(W_attn, Wa_hi, Wa_lo, C_DIM, C3_DIM);
    wconv_kernel<<<dim3(C_DIM  / 32, C_DIM / 32), 256>>>(W_o,    Wo_hi, Wo_lo, C_DIM, C_DIM);
    wconv_kernel<<<dim3(C4_DIM / 32, C_DIM / 32), 256>>>(W_fc,   Wf_hi, Wf_lo, C_DIM, C4_DIM);
    wconv_kernel<<<dim3(C_DIM / 32, C4_DIM / 32), 256>>>(W_fc2,  W2_hi, W2_lo, C4_DIM, C_DIM);

    // 1) LN1 -> h (bf16 hi/lo)
    ln_kernel<<<M_TOK, 256>>>(x, ln1_g, ln1_b, h_hi, h_lo);
    // 2) QKV = h @ W_attn + b_attn  (fp32 out)
    tc_gemm<0><<<dim3(C3_DIM / 128, M_TOK / 128), 256, GM_SMEM>>>(
        h_hi, h_lo, Wa_hi, Wa_lo, b_attn, nullptr, qkv, nullptr, nullptr, C3_DIM, C_DIM);
    // 3) attention -> y (bf16 hi/lo)
    attn_kernel<<<dim3(T_SEQ / 64, N_HEAD, 2), 256, AT_SMEM>>>(qkv, y_hi, y_lo);
    // 4) x1 = x + y @ W_o + b_o
    tc_gemm<1><<<dim3(C_DIM / 128, M_TOK / 128), 256, GM_SMEM>>>(
        y_hi, y_lo, Wo_hi, Wo_lo, b_o, x, x1, nullptr, nullptr, C_DIM, C_DIM);
    // 5) LN2 -> h (bf16 hi/lo)
    ln_kernel<<<M_TOK, 256>>>(x1, ln2_g, ln2_b, h_hi, h_lo);
    // 6) fc = gelu(h @ W_fc + b_fc) (bf16 hi/lo out)
    tc_gemm<2><<<dim3(C4_DIM / 128, M_TOK / 128), 256, GM_SMEM>>>(
        h_hi, h_lo, Wf_hi, Wf_lo, b_fc, nullptr, nullptr, fc_hi, fc_lo, C4_DIM, C_DIM);
    // 7) out = x1 + fc @ W_fc2 + b_fc2
    tc_gemm<1><<<dim3(C_DIM / 128, M_TOK / 128), 256, GM_SMEM>>>(
        fc_hi, fc_lo, W2_hi, W2_lo, b_fc2, x1, out, nullptr, nullptr, C_DIM, C4_DIM);
}

// round 5
// speedup vs baseline: 3.7212x; 2.3339x over previous
#include <cuda_runtime.h>
#include <cuda_bf16.h>
#include <math.h>
#include <stdint.h>

typedef __nv_bfloat16 bf16;

#define M_TOK   4096
#define C_DIM   1024
#define C3_DIM  3072
#define C4_DIM  4096
#define N_HEAD  16
#define HDIM    64
#define T_SEQ   2048

// ---------------------------------------------------------------------------
// Scratch (device globals; no runtime allocation)
// ---------------------------------------------------------------------------
__device__ bf16  g_h_hi  [M_TOK * C_DIM];
__device__ bf16  g_h_lo  [M_TOK * C_DIM];
__device__ bf16  g_qkv_hi[M_TOK * C3_DIM];
__device__ bf16  g_qkv_lo[M_TOK * C3_DIM];
__device__ bf16  g_y_hi  [M_TOK * C_DIM];
__device__ bf16  g_y_lo  [M_TOK * C_DIM];
__device__ float g_x1    [M_TOK * C_DIM];
__device__ bf16  g_fc_hi [M_TOK * C4_DIM];
__device__ bf16  g_fc_lo [M_TOK * C4_DIM];
// Transposed + hi/lo-split weights: [N, K] K-major
__device__ bf16  g_Wa_hi[C3_DIM * C_DIM];
__device__ bf16  g_Wa_lo[C3_DIM * C_DIM];
__device__ bf16  g_Wo_hi[C_DIM * C_DIM];
__device__ bf16  g_Wo_lo[C_DIM * C_DIM];
__device__ bf16  g_Wf_hi[C4_DIM * C_DIM];
__device__ bf16  g_Wf_lo[C4_DIM * C_DIM];
__device__ bf16  g_W2_hi[C_DIM * C4_DIM];
__device__ bf16  g_W2_lo[C_DIM * C4_DIM];

// ---------------------------------------------------------------------------
// Helpers
// ---------------------------------------------------------------------------
__device__ __forceinline__ uint32_t sm_u32(const void* p) {
    uint32_t a;
    asm("{ .reg .u64 t; cvta.to.shared.u64 t, %1; cvt.u32.u64 %0, t; }"
        : "=r"(a) : "l"(p));
    return a;
}

__device__ __forceinline__ void cp16(uint32_t s, const void* g) {
    asm volatile("cp.async.cg.shared.global [%0], [%1], 16;"
                 :: "r"(s), "l"(g) : "memory");
}
#define CP_COMMIT() asm volatile("cp.async.commit_group;" ::: "memory")
#define CP_WAIT1()  asm volatile("cp.async.wait_group 1;" ::: "memory")
#define CP_WAIT0()  asm volatile("cp.async.wait_group 0;" ::: "memory")

__device__ __forceinline__ void ldsm4(uint32_t* r, uint32_t a) {
    asm volatile("ldmatrix.sync.aligned.m8n8.x4.shared.b16 {%0,%1,%2,%3}, [%4];"
        : "=r"(r[0]), "=r"(r[1]), "=r"(r[2]), "=r"(r[3]) : "r"(a));
}
__device__ __forceinline__ void ldsm4t(uint32_t* r, uint32_t a) {
    asm volatile("ldmatrix.sync.aligned.m8n8.x4.trans.shared.b16 {%0,%1,%2,%3}, [%4];"
        : "=r"(r[0]), "=r"(r[1]), "=r"(r[2]), "=r"(r[3]) : "r"(a));
}

__device__ __forceinline__ void mma16816(float* d, const uint32_t* a,
                                         uint32_t b0, uint32_t b1) {
    asm volatile("mma.sync.aligned.m16n8k16.row.col.f32.bf16.bf16.f32 "
        "{%0,%1,%2,%3}, {%4,%5,%6,%7}, {%8,%9}, {%0,%1,%2,%3};"
        : "+f"(d[0]), "+f"(d[1]), "+f"(d[2]), "+f"(d[3])
        : "r"(a[0]), "r"(a[1]), "r"(a[2]), "r"(a[3]), "r"(b0), "r"(b1));
}

__device__ __forceinline__ float gelu_t(float x) {
    float x3 = x * x * x;
    float u = 0.7978845608028654f * (x + 0.044715f * x3);
    return 0.5f * x * (1.0f + tanhf(u));
}

__device__ __forceinline__ void split_bf16(float v, bf16& hi, bf16& lo) {
    hi = __float2bfloat16(v);
    lo = __float2bfloat16(v - __bfloat162float(hi));
}

__device__ __forceinline__ void pack_hilo(float a, float b, uint32_t& hi, uint32_t& lo) {
    bf16 ha = __float2bfloat16(a), hb = __float2bfloat16(b);
    bf16 la = __float2bfloat16(a - __bfloat162float(ha));
    bf16 lb = __float2bfloat16(b - __bfloat162float(hb));
    __nv_bfloat162 vh(ha, hb), vl(la, lb);
    hi = *(uint32_t*)&vh; lo = *(uint32_t*)&vl;
}

// ---------------------------------------------------------------------------
// Weight transpose + hi/lo split: W[K,N] fp32 -> Th[N,K], Tl[N,K] bf16
// ---------------------------------------------------------------------------
__global__ void __launch_bounds__(256) wconv_kernel(
    const float* __restrict__ W, bf16* __restrict__ Th, bf16* __restrict__ Tl,
    int K, int N)
{
    __shared__ float tile[32][33];
    const int n0 = blockIdx.x * 32, k0 = blockIdx.y * 32;
    const int tx = threadIdx.x & 31, ty = threadIdx.x >> 5;
    #pragma unroll
    for (int j = 0; j < 32; j += 8)
        tile[ty + j][tx] = W[(size_t)(k0 + ty + j) * N + n0 + tx];
    __syncthreads();
    #pragma unroll
    for (int j = 0; j < 32; j += 8) {
        float v = tile[tx][ty + j];
        bf16 hi, lo; split_bf16(v, hi, lo);
        size_t idx = (size_t)(n0 + ty + j) * K + k0 + tx;
        Th[idx] = hi; Tl[idx] = lo;
    }
}

// ---------------------------------------------------------------------------
// LayerNorm -> bf16 hi/lo output
// ---------------------------------------------------------------------------
__global__ void __launch_bounds__(256) ln_kernel(
    const float* __restrict__ x, const float* __restrict__ g,
    const float* __restrict__ b, bf16* __restrict__ oh, bf16* __restrict__ ol)
{
    __shared__ float red_s[8], red_ss[8];
    const int row = blockIdx.x;
    const int t = threadIdx.x;
    const float* xr = x + (size_t)row * C_DIM;

    float4 v = *(const float4*)(xr + t * 4);
    float s  = v.x + v.y + v.z + v.w;
    float ss = v.x*v.x + v.y*v.y + v.z*v.z + v.w*v.w;
    #pragma unroll
    for (int o = 16; o; o >>= 1) {
        s  += __shfl_xor_sync(0xffffffffu, s,  o);
        ss += __shfl_xor_sync(0xffffffffu, ss, o);
    }
    if ((t & 31) == 0) { red_s[t >> 5] = s; red_ss[t >> 5] = ss; }
    __syncthreads();
    if (t < 32) {
        float a = (t < 8) ? red_s[t]  : 0.f;
        float c = (t < 8) ? red_ss[t] : 0.f;
        #pragma unroll
        for (int o = 4; o; o >>= 1) {
            a += __shfl_xor_sync(0xffffffffu, a, o);
            c += __shfl_xor_sync(0xffffffffu, c, o);
        }
        if (t == 0) { red_s[0] = a; red_ss[0] = c; }
    }
    __syncthreads();
    const float mu  = red_s[0]  * (1.0f / C_DIM);
    const float var = red_ss[0] * (1.0f / C_DIM) - mu * mu;
    const float inv = rsqrtf(var + 1e-5f);

    float4 gv = *(const float4*)(g + t * 4);
    float4 bv = *(const float4*)(b + t * 4);
    float o0 = (v.x - mu) * inv * gv.x + bv.x;
    float o1 = (v.y - mu) * inv * gv.y + bv.y;
    float o2 = (v.z - mu) * inv * gv.z + bv.z;
    float o3 = (v.w - mu) * inv * gv.w + bv.w;

    uint32_t h01, l01, h23, l23;
    pack_hilo(o0, o1, h01, l01);
    pack_hilo(o2, o3, h23, l23);
    size_t base = (size_t)row * C_DIM + t * 4;
    *(uint32_t*)(oh + base)     = h01;
    *(uint32_t*)(oh + base + 2) = h23;
    *(uint32_t*)(ol + base)     = l01;
    *(uint32_t*)(ol + base + 2) = l23;
}

// ---------------------------------------------------------------------------
// mma.sync bf16x3-split GEMM: C = A @ B^T (+bias [+res] [gelu] [split-out])
// MODE 0: Cf = d + bias
// MODE 1: Cf = d + bias + res
// MODE 2: Ch/Cl = split(gelu(d + bias))
// MODE 3: Ch/Cl = split(d + bias)
// ---------------------------------------------------------------------------
#define TILE_B   10240
#define STAGE_B  (4 * TILE_B)
#define GM_SMEM  (2 * STAGE_B)

template<int MODE>
__global__ void __launch_bounds__(256, 2) tc_gemm(
    const bf16* __restrict__ Ah, const bf16* __restrict__ Al,
    const bf16* __restrict__ Bh, const bf16* __restrict__ Bl,
    const float* __restrict__ bias, const float* __restrict__ res,
    float* __restrict__ Cf, bf16* __restrict__ Ch, bf16* __restrict__ Cl,
    int N, int K)
{
    extern __shared__ char smem[];
    const uint32_t sb = sm_u32(smem);
    const int t = threadIdx.x, w = t >> 5, lane = t & 31;
    const int wm = w >> 2, wn = w & 3;
    const int bn0 = blockIdx.x * 128, bm0 = blockIdx.y * 128;
    const int NC = K >> 5;

    const char* gp[4];
    gp[0] = (const char*)(Ah + (size_t)bm0 * K);
    gp[1] = (const char*)(Al + (size_t)bm0 * K);
    gp[2] = (const char*)(Bh + (size_t)bn0 * K);
    gp[3] = (const char*)(Bl + (size_t)bn0 * K);
    const size_t ldb = (size_t)K * 2;

    const int c16 = t & 3, lr = t >> 2;

    auto load_chunk = [&](int i) {
        const int k0 = i << 5;
        const uint32_t st = sb + (i & 1) * STAGE_B;
        #pragma unroll
        for (int tile = 0; tile < 4; tile++) {
            #pragma unroll
            for (int half = 0; half < 2; half++) {
                const int r = lr + half * 64;
                cp16(st + tile * TILE_B + r * 80 + c16 * 16,
                     gp[tile] + (size_t)r * ldb + (size_t)k0 * 2 + c16 * 16);
            }
        }
    };

    const uint32_t a_off = (uint32_t)(lane & 15) * 80 + (uint32_t)(lane >> 4) * 16;
    const uint32_t b_off = (uint32_t)((lane >> 4) * 8 + (lane & 7)) * 80
                         + (uint32_t)((lane >> 3) & 1) * 16;

    float acc[4][4][4];
    #pragma unroll
    for (int i = 0; i < 4; i++)
        #pragma unroll
        for (int j = 0; j < 4; j++)
            #pragma unroll
            for (int k = 0; k < 4; k++) acc[i][j][k] = 0.f;

    load_chunk(0); CP_COMMIT();
    load_chunk(1); CP_COMMIT();

    for (int i = 0; i < NC; i++) {
        CP_WAIT1();
        __syncthreads();

        const uint32_t st = sb + (i & 1) * STAGE_B;
        #pragma unroll
        for (int ks = 0; ks < 2; ks++) {
            const uint32_t kb = ks * 32;
            uint32_t bh[2][4], bl[2][4];
            #pragma unroll
            for (int g = 0; g < 2; g++) {
                uint32_t nb = (uint32_t)(wn * 32 + g * 16) * 80 + kb + b_off;
                ldsm4(bh[g], st + 2 * TILE_B + nb);
                ldsm4(bl[g], st + 3 * TILE_B + nb);
            }
            #pragma unroll
            for (int mi = 0; mi < 4; mi++) {
                uint32_t mb = (uint32_t)(wm * 64 + mi * 16) * 80 + kb + a_off;
                uint32_t ah[4], al[4];
                ldsm4(ah, st + mb);
                ldsm4(al, st + TILE_B + mb);
                #pragma unroll
                for (int nj = 0; nj < 4; nj++) {
                    const int g = nj >> 1, h2 = (nj & 1) * 2;
                    mma16816(acc[mi][nj], ah, bh[g][h2], bh[g][h2 + 1]);
                    mma16816(acc[mi][nj], ah, bl[g][h2], bl[g][h2 + 1]);
                    mma16816(acc[mi][nj], al, bh[g][h2], bh[g][h2 + 1]);
                }
            }
        }
        __syncthreads();
        if (i + 2 < NC) load_chunk(i + 2);
        CP_COMMIT();
    }

    const int rr = lane >> 2, cc = (lane & 3) * 2;
    #pragma unroll
    for (int mi = 0; mi < 4; mi++) {
        #pragma unroll
        for (int nj = 0; nj < 4; nj++) {
            const int r0 = bm0 + wm * 64 + mi * 16 + rr;
            const int c0 = bn0 + wn * 32 + nj * 8 + cc;
            const float2 b2 = *(const float2*)(bias + c0);
            float v00 = acc[mi][nj][0] + b2.x;
            float v01 = acc[mi][nj][1] + b2.y;
            float v10 = acc[mi][nj][2] + b2.x;
            float v11 = acc[mi][nj][3] + b2.y;
            if (MODE == 1) {
                const float2 r2a = *(const float2*)(res + (size_t)r0 * N + c0);
                const float2 r2b = *(const float2*)(res + (size_t)(r0 + 8) * N + c0);
                v00 += r2a.x; v01 += r2a.y; v10 += r2b.x; v11 += r2b.y;
            }
            if (MODE >= 2) {
                if (MODE == 2) {
                    v00 = gelu_t(v00); v01 = gelu_t(v01);
                    v10 = gelu_t(v10); v11 = gelu_t(v11);
                }
                uint32_t hA, lA, hB, lB;
                pack_hilo(v00, v01, hA, lA);
                pack_hilo(v10, v11, hB, lB);
                *(uint32_t*)(Ch + (size_t)r0 * N + c0)       = hA;
                *(uint32_t*)(Cl + (size_t)r0 * N + c0)       = lA;
                *(uint32_t*)(Ch + (size_t)(r0 + 8) * N + c0) = hB;
                *(uint32_t*)(Cl + (size_t)(r0 + 8) * N + c0) = lB;
            } else {
                *(float2*)(Cf + (size_t)r0 * N + c0)       = make_float2(v00, v01);
                *(float2*)(Cf + (size_t)(r0 + 8) * N + c0) = make_float2(v10, v11);
            }
        }
    }
}

// ---------------------------------------------------------------------------
// Tensor-core causal flash attention.
// Grid (T/128, H, B), 256 threads (8 warps x 16 q-rows). KV tile 64.
// K/V hi/lo in smem, rows padded to 144B (ldmatrix conflict-free),
// double-buffered cp.async. S = QhKh+QhKl+QlKh; PV = PhVh+PhVl+PlVh.
// ---------------------------------------------------------------------------
#define AT_TILE  9216                    // 64 rows x 144B
#define AT_STAGE (4 * AT_TILE)           // Kh, Kl, Vh, Vl
#define AT_SMEM  (2 * AT_STAGE)          // 73728

__global__ void __launch_bounds__(256) attn_tc(
    const bf16* __restrict__ qvh, const bf16* __restrict__ qvl,
    bf16* __restrict__ yh, bf16* __restrict__ yl)
{
    extern __shared__ char smem[];
    const uint32_t sb = sm_u32(smem);
    const int qt = blockIdx.x, h = blockIdx.y, b = blockIdx.z;
    const int t = threadIdx.x, lane = t & 31;
    const int strip = qt * 128 + (t >> 5) * 16;
    const int r0 = lane >> 2, q2 = (lane & 3) << 1;

    const size_t base2 = (size_t)(b * T_SEQ) * C3_DIM + h * HDIM;

    // Q fragments (direct from gmem)
    uint32_t Qh[4][4], Ql[4][4];
    {
        const size_t ra = base2 + (size_t)(strip + r0) * C3_DIM;
        const size_t rb = ra + (size_t)8 * C3_DIM;
        #pragma unroll
        for (int kt = 0; kt < 4; kt++) {
            const int c0 = kt * 16 + q2;
            Qh[kt][0] = *(const uint32_t*)(qvh + ra + c0);
            Qh[kt][1] = *(const uint32_t*)(qvh + rb + c0);
            Qh[kt][2] = *(const uint32_t*)(qvh + ra + c0 + 8);
            Qh[kt][3] = *(const uint32_t*)(qvh + rb + c0 + 8);
            Ql[kt][0] = *(const uint32_t*)(qvl + ra + c0);
            Ql[kt][1] = *(const uint32_t*)(qvl + rb + c0);
            Ql[kt][2] = *(const uint32_t*)(qvl + ra + c0 + 8);
            Ql[kt][3] = *(const uint32_t*)(qvl + rb + c0 + 8);
        }
    }

    float o[8][4];
    #pragma unroll
    for (int i = 0; i < 8; i++)
        #pragma unroll
        for (int e = 0; e < 4; e++) o[i][e] = 0.f;
    float mA = -1e30f, mB = -1e30f, lA = 0.f, lB = 0.f;
    const int jmax = 2 * qt + 1;

    auto load_kv = [&](int j) {
        const uint32_t st = sb + (j & 1) * AT_STAGE;
        #pragma unroll
        for (int i = 0; i < 2; i++) {
            const int id = t + 256 * i;
            const int row = id >> 3, c = id & 7;
            const size_t src = base2 + (size_t)(j * 64 + row) * C3_DIM + c * 8;
            const uint32_t dst = st + row * 144 + c * 16;
            cp16(dst,               qvh + src + C_DIM);
            cp16(dst + AT_TILE,     qvl + src + C_DIM);
            cp16(dst + 2 * AT_TILE, qvh + src + 2 * C_DIM);
            cp16(dst + 3 * AT_TILE, qvl + src + 2 * C_DIM);
        }
    };

    load_kv(0); CP_COMMIT();

    for (int j = 0; j <= jmax; j++) {
        if (j < jmax) {
            load_kv(j + 1); CP_COMMIT();
            CP_WAIT1();
        } else {
            CP_WAIT0();
        }
        __syncthreads();

        const int jb = j * 64;
        if (jb <= strip + 15) {
            const uint32_t st = sb + (j & 1) * AT_STAGE;
            float s[8][4];
            #pragma unroll
            for (int i = 0; i < 8; i++)
                #pragma unroll
                for (int e = 0; e < 4; e++) s[i][e] = 0.f;

            // ---- S = Q K^T ----
            const uint32_t koffb = st + ((lane >> 4) * 8 + (lane & 7)) * 144
                                 + ((lane >> 3) & 1) * 16;
            #pragma unroll
            for (int kt = 0; kt < 4; kt++) {
                #pragma unroll
                for (int g = 0; g < 4; g++) {
                    const uint32_t off = koffb + g * (16 * 144) + kt * 32;
                    uint32_t kh4[4], kl4[4];
                    ldsm4(kh4, off);
                    ldsm4(kl4, off + AT_TILE);
                    mma16816(s[2*g],   Qh[kt], kh4[0], kh4[1]);
                    mma16816(s[2*g],   Qh[kt], kl4[0], kl4[1]);
                    mma16816(s[2*g],   Ql[kt], kh4[0], kh4[1]);
                    mma16816(s[2*g+1], Qh[kt], kh4[2], kh4[3]);
                    mma16816(s[2*g+1], Qh[kt], kl4[2], kl4[3]);
                    mma16816(s[2*g+1], Ql[kt], kh4[2], kh4[3]);
                }
            }

            // ---- softmax (online) ----
            const bool domask = (jb + 63 > strip);
            const int rowA = strip + r0, rowB = rowA + 8;
            float mtA = -1e30f, mtB = -1e30f;
            #pragma unroll
            for (int nj = 0; nj < 8; nj++) {
                #pragma unroll
                for (int e = 0; e < 4; e++) s[nj][e] *= 0.125f;
                if (domask) {
                    const int col0 = jb + nj * 8 + q2;
                    if (col0     > rowA) s[nj][0] = -1e30f;
                    if (col0 + 1 > rowA) s[nj][1] = -1e30f;
                    if (col0     > rowB) s[nj][2] = -1e30f;
                    if (col0 + 1 > rowB) s[nj][3] = -1e30f;
                }
                mtA = fmaxf(mtA, fmaxf(s[nj][0], s[nj][1]));
                mtB = fmaxf(mtB, fmaxf(s[nj][2], s[nj][3]));
            }
            mtA = fmaxf(mtA, __shfl_xor_sync(0xffffffffu, mtA, 1));
            mtA = fmaxf(mtA, __shfl_xor_sync(0xffffffffu, mtA, 2));
            mtB = fmaxf(mtB, __shfl_xor_sync(0xffffffffu, mtB, 1));
            mtB = fmaxf(mtB, __shfl_xor_sync(0xffffffffu, mtB, 2));
            const float mnA = fmaxf(mA, mtA), mnB = fmaxf(mB, mtB);
            const float aA = __expf(mA - mnA), aB = __expf(mB - mnB);

            float sA = 0.f, sB = 0.f;
            uint32_t ph[4][4], pl[4][4];
            #pragma unroll
            for (int g = 0; g < 4; g++) {
                float p00 = __expf(s[2*g][0]   - mnA), p01 = __expf(s[2*g][1]   - mnA);
                float p10 = __expf(s[2*g][2]   - mnB), p11 = __expf(s[2*g][3]   - mnB);
                float p20 = __expf(s[2*g+1][0] - mnA), p21 = __expf(s[2*g+1][1] - mnA);
                float p30 = __expf(s[2*g+1][2] - mnB), p31 = __expf(s[2*g+1][3] - mnB);
                sA += p00 + p01 + p20 + p21;
                sB += p10 + p11 + p30 + p31;
                pack_hilo(p00, p01, ph[g][0], pl[g][0]);
                pack_hilo(p10, p11, ph[g][1], pl[g][1]);
                pack_hilo(p20, p21, ph[g][2], pl[g][2]);
                pack_hilo(p30, p31, ph[g][3], pl[g][3]);
            }
            sA += __shfl_xor_sync(0xffffffffu, sA, 1);
            sA += __shfl_xor_sync(0xffffffffu, sA, 2);
            sB += __shfl_xor_sync(0xffffffffu, sB, 1);
            sB += __shfl_xor_sync(0xffffffffu, sB, 2);
            lA = lA * aA + sA;
            lB = lB * aB + sB;
            mA = mnA; mB = mnB;
            #pragma unroll
            for (int nj = 0; nj < 8; nj++) {
                o[nj][0] *= aA; o[nj][1] *= aA;
                o[nj][2] *= aB; o[nj][3] *= aB;
            }

            // ---- O += P V ----
            const uint32_t voffb = st + 2 * AT_TILE + (lane & 15) * 144
                                 + (lane >> 4) * 16;
            #pragma unroll
            for (int g = 0; g < 4; g++) {
                #pragma unroll
                for (int nh = 0; nh < 4; nh++) {
                    const uint32_t off = voffb + g * (16 * 144) + nh * 32;
                    uint32_t vh4[4], vl4[4];
                    ldsm4t(vh4, off);
                    ldsm4t(vl4, off + AT_TILE);
                    mma16816(o[2*nh],   ph[g], vh4[0], vh4[1]);
                    mma16816(o[2*nh],   ph[g], vl4[0], vl4[1]);
                    mma16816(o[2*nh],   pl[g], vh4[0], vh4[1]);
                    mma16816(o[2*nh+1], ph[g], vh4[2], vh4[3]);
                    mma16816(o[2*nh+1], ph[g], vl4[2], vl4[3]);
                    mma16816(o[2*nh+1], pl[g], vh4[2], vh4[3]);
                }
            }
        }
        __syncthreads();
    }

    const float iA = 1.f / lA, iB = 1.f / lB;
    const size_t oA = (size_t)(b * T_SEQ + strip + r0) * C_DIM + h * HDIM;
    const size_t oB = oA + (size_t)8 * C_DIM;
    #pragma unroll
    for (int nj = 0; nj < 8; nj++) {
        const int col = nj * 8 + q2;
        uint32_t hA, lAa, hB, lBb;
        pack_hilo(o[nj][0] * iA, o[nj][1] * iA, hA, lAa);
        pack_hilo(o[nj][2] * iB, o[nj][3] * iB, hB, lBb);
        *(uint32_t*)(yh + oA + col) = hA;
        *(uint32_t*)(yl + oA + col) = lAa;
        *(uint32_t*)(yh + oB + col) = hB;
        *(uint32_t*)(yl + oB + col) = lBb;
    }
}

// ---------------------------------------------------------------------------
// Launch
// ---------------------------------------------------------------------------
extern "C" void kernel_launch(void* const* d_in, const int* in_sizes, int n_in,
                              void* d_out, int out_size)
{
    const float* x      = (const float*)d_in[0];
    const float* ln1_g  = (const float*)d_in[1];
    const float* ln1_b  = (const float*)d_in[2];
    const float* W_attn = (const float*)d_in[3];
    const float* b_attn = (const float*)d_in[4];
    const float* W_o    = (const float*)d_in[5];
    const float* b_o    = (const float*)d_in[6];
    const float* ln2_g  = (const float*)d_in[7];
    const float* ln2_b  = (const float*)d_in[8];
    const float* W_fc   = (const float*)d_in[9];
    const float* b_fc   = (const float*)d_in[10];
    const float* W_fc2  = (const float*)d_in[11];
    const float* b_fc2  = (const float*)d_in[12];
    float* out = (float*)d_out;

    bf16 *h_hi, *h_lo, *qkv_hi, *qkv_lo, *y_hi, *y_lo, *fc_hi, *fc_lo;
    bf16 *Wa_hi, *Wa_lo, *Wo_hi, *Wo_lo, *Wf_hi, *Wf_lo, *W2_hi, *W2_lo;
    float *x1;
    cudaGetSymbolAddress((void**)&h_hi,   g_h_hi);
    cudaGetSymbolAddress((void**)&h_lo,   g_h_lo);
    cudaGetSymbolAddress((void**)&qkv_hi, g_qkv_hi);
    cudaGetSymbolAddress((void**)&qkv_lo, g_qkv_lo);
    cudaGetSymbolAddress((void**)&y_hi,   g_y_hi);
    cudaGetSymbolAddress((void**)&y_lo,   g_y_lo);
    cudaGetSymbolAddress((void**)&x1,     g_x1);
    cudaGetSymbolAddress((void**)&fc_hi,  g_fc_hi);
    cudaGetSymbolAddress((void**)&fc_lo,  g_fc_lo);
    cudaGetSymbolAddress((void**)&Wa_hi,  g_Wa_hi);
    cudaGetSymbolAddress((void**)&Wa_lo,  g_Wa_lo);
    cudaGetSymbolAddress((void**)&Wo_hi,  g_Wo_hi);
    cudaGetSymbolAddress((void**)&Wo_lo,  g_Wo_lo);
    cudaGetSymbolAddress((void**)&Wf_hi,  g_Wf_hi);
    cudaGetSymbolAddress((void**)&Wf_lo,  g_Wf_lo);
    cudaGetSymbolAddress((void**)&W2_hi,  g_W2_hi);
    cudaGetSymbolAddress((void**)&W2_lo,  g_W2_lo);

    cudaFuncSetAttribute(attn_tc,    cudaFuncAttributeMaxDynamicSharedMemorySize, AT_SMEM);
    cudaFuncSetAttribute(tc_gemm<0>, cudaFuncAttributeMaxDynamicSharedMemorySize, GM_SMEM);
    cudaFuncSetAttribute(tc_gemm<1>, cudaFuncAttributeMaxDynamicSharedMemorySize, GM_SMEM);
    cudaFuncSetAttribute(tc_gemm<2>, cudaFuncAttributeMaxDynamicSharedMemorySize, GM_SMEM);
    cudaFuncSetAttribute(tc_gemm<3>, cudaFuncAttributeMaxDynamicSharedMemorySize, GM_SMEM);

    // Weight prep
    wconv_kernel<<<dim3(C3_DIM / 32, C_DIM / 32), 256>>>(W_attn, Wa_hi, Wa_lo, C_DIM, C3_DIM);
    wconv_kernel<<<dim3(C_DIM  / 32, C_DIM / 32), 256>>>(W_o,    Wo_hi, Wo_lo, C_DIM, C_DIM);
    wconv_kernel<<<dim3(C4_DIM / 32, C_DIM / 32), 256>>>(W_fc,   Wf_hi, Wf_lo, C_DIM, C4_DIM);
    wconv_kernel<<<dim3(C_DIM / 32, C4_DIM / 32), 256>>>(W_fc2,  W2_hi, W2_lo, C4_DIM, C_DIM);

    // 1) LN1
    ln_kernel<<<M_TOK, 256>>>(x, ln1_g, ln1_b, h_hi, h_lo);
    // 2) QKV (split bf16 output)
    tc_gemm<3><<<dim3(C3_DIM / 128, M_TOK / 128), 256, GM_SMEM>>>(
        h_hi, h_lo, Wa_hi, Wa_lo, b_attn, nullptr, nullptr, qkv_hi, qkv_lo, C3_DIM, C_DIM);
    // 3) tensor-core flash attention
    attn_tc<<<dim3(T_SEQ / 128, N_HEAD, 2), 256, AT_SMEM>>>(qkv_hi, qkv_lo, y_hi, y_lo);
    // 4) x1 = x + y @ W_o + b_o
    tc_gemm<1><<<dim3(C_DIM / 128, M_TOK / 128), 256, GM_SMEM>>>(
        y_hi, y_lo, Wo_hi, Wo_lo, b_o, x, x1, nullptr, nullptr, C_DIM, C_DIM);
    // 5) LN2
    ln_kernel<<<M_TOK, 256>>>(x1, ln2_g, ln2_b, h_hi, h_lo);
    // 6) fc = gelu(h @ W_fc + b_fc)
    tc_gemm<2><<<dim3(C4_DIM / 128, M_TOK / 128), 256, GM_SMEM>>>(
        h_hi, h_lo, Wf_hi, Wf_lo, b_fc, nullptr, nullptr, fc_hi, fc_lo, C4_DIM, C_DIM);
    // 7) out = x1 + fc @ W_fc2 + b_fc2
    tc_gemm<1><<<dim3(C_DIM / 128, M_TOK / 128), 256, GM_SMEM>>>(
        fc_hi, fc_lo, W2_hi, W2_lo, b_fc2, x1, out, nullptr, nullptr, C_DIM, C4_DIM);
}

// round 6
// speedup vs baseline: 4.9740x; 1.3367x over previous
#include <cuda_runtime.h>
#include <cuda_fp16.h>
#include <math.h>
#include <stdint.h>

#define M_TOK   4096
#define C_DIM   1024
#define C3_DIM  3072
#define C4_DIM  4096
#define N_HEAD  16
#define HDIM    64
#define T_SEQ   2048

// ---------------------------------------------------------------------------
// Scratch (device globals; no runtime allocation)
// ---------------------------------------------------------------------------
__device__ __half g_h_hi  [M_TOK * C_DIM];
__device__ __half g_h_lo  [M_TOK * C_DIM];
__device__ __half g_qkv_hi[M_TOK * C3_DIM];
__device__ __half g_qkv_lo[M_TOK * C3_DIM];
__device__ __half g_y_hi  [M_TOK * C_DIM];
__device__ __half g_y_lo  [M_TOK * C_DIM];
__device__ float  g_x1    [M_TOK * C_DIM];
__device__ __half g_fc_hi [M_TOK * C4_DIM];
__device__ __half g_fc_lo [M_TOK * C4_DIM];
// Transposed fp16 weights: [N, K] K-major (hi only)
__device__ __half g_Wa[C3_DIM * C_DIM];
__device__ __half g_Wo[C_DIM * C_DIM];
__device__ __half g_Wf[C4_DIM * C_DIM];
__device__ __half g_W2[C_DIM * C4_DIM];

// ---------------------------------------------------------------------------
// Helpers
// ---------------------------------------------------------------------------
__device__ __forceinline__ uint32_t sm_u32(const void* p) {
    uint32_t a;
    asm("{ .reg .u64 t; cvta.to.shared.u64 t, %1; cvt.u32.u64 %0, t; }"
        : "=r"(a) : "l"(p));
    return a;
}

__device__ __forceinline__ void cp16(uint32_t s, const void* g) {
    asm volatile("cp.async.cg.shared.global [%0], [%1], 16;"
                 :: "r"(s), "l"(g) : "memory");
}
#define CP_COMMIT() asm volatile("cp.async.commit_group;" ::: "memory")
#define CP_WAIT1()  asm volatile("cp.async.wait_group 1;" ::: "memory")
#define CP_WAIT0()  asm volatile("cp.async.wait_group 0;" ::: "memory")

__device__ __forceinline__ void ldsm4(uint32_t* r, uint32_t a) {
    asm volatile("ldmatrix.sync.aligned.m8n8.x4.shared.b16 {%0,%1,%2,%3}, [%4];"
        : "=r"(r[0]), "=r"(r[1]), "=r"(r[2]), "=r"(r[3]) : "r"(a));
}
__device__ __forceinline__ void ldsm4t(uint32_t* r, uint32_t a) {
    asm volatile("ldmatrix.sync.aligned.m8n8.x4.trans.shared.b16 {%0,%1,%2,%3}, [%4];"
        : "=r"(r[0]), "=r"(r[1]), "=r"(r[2]), "=r"(r[3]) : "r"(a));
}

__device__ __forceinline__ void mma16816(float* d, const uint32_t* a,
                                         uint32_t b0, uint32_t b1) {
    asm volatile("mma.sync.aligned.m16n8k16.row.col.f32.f16.f16.f32 "
        "{%0,%1,%2,%3}, {%4,%5,%6,%7}, {%8,%9}, {%0,%1,%2,%3};"
        : "+f"(d[0]), "+f"(d[1]), "+f"(d[2]), "+f"(d[3])
        : "r"(a[0]), "r"(a[1]), "r"(a[2]), "r"(a[3]), "r"(b0), "r"(b1));
}

__device__ __forceinline__ float gelu_t(float x) {
    float x3 = x * x * x;
    float u = 0.7978845608028654f * (x + 0.044715f * x3);
    return 0.5f * x * (1.0f + tanhf(u));
}

__device__ __forceinline__ void pack_hilo(float a, float b, uint32_t& hi, uint32_t& lo) {
    __half ha = __float2half_rn(a), hb = __float2half_rn(b);
    __half la = __float2half_rn(a - __half2float(ha));
    __half lb = __float2half_rn(b - __half2float(hb));
    __half2 vh = __halves2half2(ha, hb), vl = __halves2half2(la, lb);
    hi = *(uint32_t*)&vh; lo = *(uint32_t*)&vl;
}

// ---------------------------------------------------------------------------
// Weight transpose to fp16: W[K,N] fp32 -> T[N,K] fp16
// ---------------------------------------------------------------------------
__global__ void __launch_bounds__(256) wconv_kernel(
    const float* __restrict__ W, __half* __restrict__ T, int K, int N)
{
    __shared__ float tile[32][33];
    const int n0 = blockIdx.x * 32, k0 = blockIdx.y * 32;
    const int tx = threadIdx.x & 31, ty = threadIdx.x >> 5;
    #pragma unroll
    for (int j = 0; j < 32; j += 8)
        tile[ty + j][tx] = W[(size_t)(k0 + ty + j) * N + n0 + tx];
    __syncthreads();
    #pragma unroll
    for (int j = 0; j < 32; j += 8)
        T[(size_t)(n0 + ty + j) * K + k0 + tx] = __float2half_rn(tile[tx][ty + j]);
}

// ---------------------------------------------------------------------------
// LayerNorm -> fp16 hi/lo output
// ---------------------------------------------------------------------------
__global__ void __launch_bounds__(256) ln_kernel(
    const float* __restrict__ x, const float* __restrict__ g,
    const float* __restrict__ b, __half* __restrict__ oh, __half* __restrict__ ol)
{
    __shared__ float red_s[8], red_ss[8];
    const int row = blockIdx.x;
    const int t = threadIdx.x;
    const float* xr = x + (size_t)row * C_DIM;

    float4 v = *(const float4*)(xr + t * 4);
    float s  = v.x + v.y + v.z + v.w;
    float ss = v.x*v.x + v.y*v.y + v.z*v.z + v.w*v.w;
    #pragma unroll
    for (int o = 16; o; o >>= 1) {
        s  += __shfl_xor_sync(0xffffffffu, s,  o);
        ss += __shfl_xor_sync(0xffffffffu, ss, o);
    }
    if ((t & 31) == 0) { red_s[t >> 5] = s; red_ss[t >> 5] = ss; }
    __syncthreads();
    if (t < 32) {
        float a = (t < 8) ? red_s[t]  : 0.f;
        float c = (t < 8) ? red_ss[t] : 0.f;
        #pragma unroll
        for (int o = 4; o; o >>= 1) {
            a += __shfl_xor_sync(0xffffffffu, a, o);
            c += __shfl_xor_sync(0xffffffffu, c, o);
        }
        if (t == 0) { red_s[0] = a; red_ss[0] = c; }
    }
    __syncthreads();
    const float mu  = red_s[0]  * (1.0f / C_DIM);
    const float var = red_ss[0] * (1.0f / C_DIM) - mu * mu;
    const float inv = rsqrtf(var + 1e-5f);

    float4 gv = *(const float4*)(g + t * 4);
    float4 bv = *(const float4*)(b + t * 4);
    float o0 = (v.x - mu) * inv * gv.x + bv.x;
    float o1 = (v.y - mu) * inv * gv.y + bv.y;
    float o2 = (v.z - mu) * inv * gv.z + bv.z;
    float o3 = (v.w - mu) * inv * gv.w + bv.w;

    uint32_t h01, l01, h23, l23;
    pack_hilo(o0, o1, h01, l01);
    pack_hilo(o2, o3, h23, l23);
    size_t base = (size_t)row * C_DIM + t * 4;
    *(uint32_t*)(oh + base)     = h01;
    *(uint32_t*)(oh + base + 2) = h23;
    *(uint32_t*)(ol + base)     = l01;
    *(uint32_t*)(ol + base + 2) = l23;
}

// ---------------------------------------------------------------------------
// mma.sync fp16 GEMM, A 2-term split, B hi-only:
//   C = (Ah + Al) @ Bh^T  (+bias [+res] [gelu] [split-out])
// CTA 128x128x32, 8 warps (2x4), warp tile 64x32.
// 3-stage cp.async pipeline, ONE __syncthreads per K-chunk.
// MODE 0: Cf = d + bias
// MODE 1: Cf = d + bias + res
// MODE 2: Ch/Cl = split(gelu(d + bias))
// MODE 3: Ch/Cl = split(d + bias)
// ---------------------------------------------------------------------------
#define TILE_B   10240                // 128 rows x 80 bytes
#define STAGE_B  (3 * TILE_B)         // Ah, Al, Bh  = 30720
#define GM_SMEM  (3 * STAGE_B)        // 3 stages    = 92160

template<int MODE>
__global__ void __launch_bounds__(256, 2) tc_gemm(
    const __half* __restrict__ Ah, const __half* __restrict__ Al,
    const __half* __restrict__ Bh,
    const float* __restrict__ bias, const float* __restrict__ res,
    float* __restrict__ Cf, __half* __restrict__ Ch, __half* __restrict__ Cl,
    int N, int K)
{
    extern __shared__ char smem[];
    const uint32_t sb = sm_u32(smem);
    const int t = threadIdx.x, w = t >> 5, lane = t & 31;
    const int wm = w >> 2, wn = w & 3;
    const int bn0 = blockIdx.x * 128, bm0 = blockIdx.y * 128;
    const int NC = K >> 5;

    const char* gp[3];
    gp[0] = (const char*)(Ah + (size_t)bm0 * K);
    gp[1] = (const char*)(Al + (size_t)bm0 * K);
    gp[2] = (const char*)(Bh + (size_t)bn0 * K);
    const size_t ldb = (size_t)K * 2;

    const int c16 = t & 3, lr = t >> 2;

    auto load_chunk = [&](int i) {
        const int k0 = i << 5;
        const uint32_t st = sb + (i % 3) * STAGE_B;
        #pragma unroll
        for (int tile = 0; tile < 3; tile++) {
            #pragma unroll
            for (int half = 0; half < 2; half++) {
                const int r = lr + half * 64;
                cp16(st + tile * TILE_B + r * 80 + c16 * 16,
                     gp[tile] + (size_t)r * ldb + (size_t)k0 * 2 + c16 * 16);
            }
        }
    };

    const uint32_t a_off = (uint32_t)(lane & 15) * 80 + (uint32_t)(lane >> 4) * 16;
    const uint32_t b_off = (uint32_t)((lane >> 4) * 8 + (lane & 7)) * 80
                         + (uint32_t)((lane >> 3) & 1) * 16;

    float acc[4][4][4];
    #pragma unroll
    for (int i = 0; i < 4; i++)
        #pragma unroll
        for (int j = 0; j < 4; j++)
            #pragma unroll
            for (int k = 0; k < 4; k++) acc[i][j][k] = 0.f;

    load_chunk(0); CP_COMMIT();
    load_chunk(1); CP_COMMIT();

    for (int i = 0; i < NC; i++) {
        if (i < NC - 1) { CP_WAIT1(); } else { CP_WAIT0(); }
        __syncthreads();
        if (i + 2 < NC) { load_chunk(i + 2); CP_COMMIT(); }

        const uint32_t st = sb + (i % 3) * STAGE_B;
        #pragma unroll
        for (int ks = 0; ks < 2; ks++) {
            const uint32_t kb = ks * 32;
            uint32_t bh[2][4];
            #pragma unroll
            for (int g = 0; g < 2; g++) {
                uint32_t nb = (uint32_t)(wn * 32 + g * 16) * 80 + kb + b_off;
                ldsm4(bh[g], st + 2 * TILE_B + nb);
            }
            #pragma unroll
            for (int mi = 0; mi < 4; mi++) {
                uint32_t mb = (uint32_t)(wm * 64 + mi * 16) * 80 + kb + a_off;
                uint32_t ah[4], al[4];
                ldsm4(ah, st + mb);
                ldsm4(al, st + TILE_B + mb);
                #pragma unroll
                for (int nj = 0; nj < 4; nj++) {
                    const int g = nj >> 1, h2 = (nj & 1) * 2;
                    mma16816(acc[mi][nj], ah, bh[g][h2], bh[g][h2 + 1]);
                    mma16816(acc[mi][nj], al, bh[g][h2], bh[g][h2 + 1]);
                }
            }
        }
    }

    const int rr = lane >> 2, cc = (lane & 3) * 2;
    #pragma unroll
    for (int mi = 0; mi < 4; mi++) {
        #pragma unroll
        for (int nj = 0; nj < 4; nj++) {
            const int r0 = bm0 + wm * 64 + mi * 16 + rr;
            const int c0 = bn0 + wn * 32 + nj * 8 + cc;
            const float2 b2 = *(const float2*)(bias + c0);
            float v00 = acc[mi][nj][0] + b2.x;
            float v01 = acc[mi][nj][1] + b2.y;
            float v10 = acc[mi][nj][2] + b2.x;
            float v11 = acc[mi][nj][3] + b2.y;
            if (MODE == 1) {
                const float2 r2a = *(const float2*)(res + (size_t)r0 * N + c0);
                const float2 r2b = *(const float2*)(res + (size_t)(r0 + 8) * N + c0);
                v00 += r2a.x; v01 += r2a.y; v10 += r2b.x; v11 += r2b.y;
            }
            if (MODE >= 2) {
                if (MODE == 2) {
                    v00 = gelu_t(v00); v01 = gelu_t(v01);
                    v10 = gelu_t(v10); v11 = gelu_t(v11);
                }
                uint32_t hA, lA, hB, lB;
                pack_hilo(v00, v01, hA, lA);
                pack_hilo(v10, v11, hB, lB);
                *(uint32_t*)(Ch + (size_t)r0 * N + c0)       = hA;
                *(uint32_t*)(Cl + (size_t)r0 * N + c0)       = lA;
                *(uint32_t*)(Ch + (size_t)(r0 + 8) * N + c0) = hB;
                *(uint32_t*)(Cl + (size_t)(r0 + 8) * N + c0) = lB;
            } else {
                *(float2*)(Cf + (size_t)r0 * N + c0)       = make_float2(v00, v01);
                *(float2*)(Cf + (size_t)(r0 + 8) * N + c0) = make_float2(v10, v11);
            }
        }
    }
}

// ---------------------------------------------------------------------------
// Tensor-core causal flash attention (fp16, Q/P 2-term split, K/V hi-only).
// Grid (T/128, H, B), 256 threads (8 warps x 16 q-rows). KV tile 64.
// ---------------------------------------------------------------------------
#define AT_TILE  9216                    // 64 rows x 144B
#define AT_STAGE (2 * AT_TILE)           // Kh, Vh
#define AT_SMEM  (2 * AT_STAGE)          // 36864

__global__ void __launch_bounds__(256) attn_tc(
    const __half* __restrict__ qvh, const __half* __restrict__ qvl,
    __half* __restrict__ yh, __half* __restrict__ yl)
{
    extern __shared__ char smem[];
    const uint32_t sb = sm_u32(smem);
    const int qt = blockIdx.x, h = blockIdx.y, b = blockIdx.z;
    const int t = threadIdx.x, lane = t & 31;
    const int strip = qt * 128 + (t >> 5) * 16;
    const int r0 = lane >> 2, q2 = (lane & 3) << 1;

    const size_t base2 = (size_t)(b * T_SEQ) * C3_DIM + h * HDIM;

    uint32_t Qh[4][4], Ql[4][4];
    {
        const size_t ra = base2 + (size_t)(strip + r0) * C3_DIM;
        const size_t rb = ra + (size_t)8 * C3_DIM;
        #pragma unroll
        for (int kt = 0; kt < 4; kt++) {
            const int c0 = kt * 16 + q2;
            Qh[kt][0] = *(const uint32_t*)(qvh + ra + c0);
            Qh[kt][1] = *(const uint32_t*)(qvh + rb + c0);
            Qh[kt][2] = *(const uint32_t*)(qvh + ra + c0 + 8);
            Qh[kt][3] = *(const uint32_t*)(qvh + rb + c0 + 8);
            Ql[kt][0] = *(const uint32_t*)(qvl + ra + c0);
            Ql[kt][1] = *(const uint32_t*)(qvl + rb + c0);
            Ql[kt][2] = *(const uint32_t*)(qvl + ra + c0 + 8);
            Ql[kt][3] = *(const uint32_t*)(qvl + rb + c0 + 8);
        }
    }

    float o[8][4];
    #pragma unroll
    for (int i = 0; i < 8; i++)
        #pragma unroll
        for (int e = 0; e < 4; e++) o[i][e] = 0.f;
    float mA = -1e30f, mB = -1e30f, lA = 0.f, lB = 0.f;
    const int jmax = 2 * qt + 1;

    auto load_kv = [&](int j) {
        const uint32_t st = sb + (j & 1) * AT_STAGE;
        #pragma unroll
        for (int i = 0; i < 2; i++) {
            const int id = t + 256 * i;
            const int row = id >> 3, c = id & 7;
            const size_t src = base2 + (size_t)(j * 64 + row) * C3_DIM + c * 8;
            const uint32_t dst = st + row * 144 + c * 16;
            cp16(dst,           qvh + src + C_DIM);       // Kh
            cp16(dst + AT_TILE, qvh + src + 2 * C_DIM);   // Vh
        }
    };

    load_kv(0); CP_COMMIT();

    for (int j = 0; j <= jmax; j++) {
        if (j < jmax) {
            load_kv(j + 1); CP_COMMIT();
            CP_WAIT1();
        } else {
            CP_WAIT0();
        }
        __syncthreads();

        const int jb = j * 64;
        if (jb <= strip + 15) {
            const uint32_t st = sb + (j & 1) * AT_STAGE;
            float s[8][4];
            #pragma unroll
            for (int i = 0; i < 8; i++)
                #pragma unroll
                for (int e = 0; e < 4; e++) s[i][e] = 0.f;

            // ---- S = Q K^T ----
            const uint32_t koffb = st + ((lane >> 4) * 8 + (lane & 7)) * 144
                                 + ((lane >> 3) & 1) * 16;
            #pragma unroll
            for (int kt = 0; kt < 4; kt++) {
                #pragma unroll
                for (int g = 0; g < 4; g++) {
                    const uint32_t off = koffb + g * (16 * 144) + kt * 32;
                    uint32_t kh4[4];
                    ldsm4(kh4, off);
                    mma16816(s[2*g],   Qh[kt], kh4[0], kh4[1]);
                    mma16816(s[2*g],   Ql[kt], kh4[0], kh4[1]);
                    mma16816(s[2*g+1], Qh[kt], kh4[2], kh4[3]);
                    mma16816(s[2*g+1], Ql[kt], kh4[2], kh4[3]);
                }
            }

            // ---- softmax (online) ----
            const bool domask = (jb + 63 > strip);
            const int rowA = strip + r0, rowB = rowA + 8;
            float mtA = -1e30f, mtB = -1e30f;
            #pragma unroll
            for (int nj = 0; nj < 8; nj++) {
                #pragma unroll
                for (int e = 0; e < 4; e++) s[nj][e] *= 0.125f;
                if (domask) {
                    const int col0 = jb + nj * 8 + q2;
                    if (col0     > rowA) s[nj][0] = -1e30f;
                    if (col0 + 1 > rowA) s[nj][1] = -1e30f;
                    if (col0     > rowB) s[nj][2] = -1e30f;
                    if (col0 + 1 > rowB) s[nj][3] = -1e30f;
                }
                mtA = fmaxf(mtA, fmaxf(s[nj][0], s[nj][1]));
                mtB = fmaxf(mtB, fmaxf(s[nj][2], s[nj][3]));
            }
            mtA = fmaxf(mtA, __shfl_xor_sync(0xffffffffu, mtA, 1));
            mtA = fmaxf(mtA, __shfl_xor_sync(0xffffffffu, mtA, 2));
            mtB = fmaxf(mtB, __shfl_xor_sync(0xffffffffu, mtB, 1));
            mtB = fmaxf(mtB, __shfl_xor_sync(0xffffffffu, mtB, 2));
            const float mnA = fmaxf(mA, mtA), mnB = fmaxf(mB, mtB);
            const float aA = __expf(mA - mnA), aB = __expf(mB - mnB);

            float sA = 0.f, sB = 0.f;
            uint32_t ph[4][4], pl[4][4];
            #pragma unroll
            for (int g = 0; g < 4; g++) {
                float p00 = __expf(s[2*g][0]   - mnA), p01 = __expf(s[2*g][1]   - mnA);
                float p10 = __expf(s[2*g][2]   - mnB), p11 = __expf(s[2*g][3]   - mnB);
                float p20 = __expf(s[2*g+1][0] - mnA), p21 = __expf(s[2*g+1][1] - mnA);
                float p30 = __expf(s[2*g+1][2] - mnB), p31 = __expf(s[2*g+1][3] - mnB);
                sA += p00 + p01 + p20 + p21;
                sB += p10 + p11 + p30 + p31;
                pack_hilo(p00, p01, ph[g][0], pl[g][0]);
                pack_hilo(p10, p11, ph[g][1], pl[g][1]);
                pack_hilo(p20, p21, ph[g][2], pl[g][2]);
                pack_hilo(p30, p31, ph[g][3], pl[g][3]);
            }
            sA += __shfl_xor_sync(0xffffffffu, sA, 1);
            sA += __shfl_xor_sync(0xffffffffu, sA, 2);
            sB += __shfl_xor_sync(0xffffffffu, sB, 1);
            sB += __shfl_xor_sync(0xffffffffu, sB, 2);
            lA = lA * aA + sA;
            lB = lB * aB + sB;
            mA = mnA; mB = mnB;
            #pragma unroll
            for (int nj = 0; nj < 8; nj++) {
                o[nj][0] *= aA; o[nj][1] *= aA;
                o[nj][2] *= aB; o[nj][3] *= aB;
            }

            // ---- O += P V ----
            const uint32_t voffb = st + AT_TILE + (lane & 15) * 144
                                 + (lane >> 4) * 16;
            #pragma unroll
            for (int g = 0; g < 4; g++) {
                #pragma unroll
                for (int nh = 0; nh < 4; nh++) {
                    const uint32_t off = voffb + g * (16 * 144) + nh * 32;
                    uint32_t vh4[4];
                    ldsm4t(vh4, off);
                    mma16816(o[2*nh],   ph[g], vh4[0], vh4[1]);
                    mma16816(o[2*nh],   pl[g], vh4[0], vh4[1]);
                    mma16816(o[2*nh+1], ph[g], vh4[2], vh4[3]);
                    mma16816(o[2*nh+1], pl[g], vh4[2], vh4[3]);
                }
            }
        }
        __syncthreads();
    }

    const float iA = 1.f / lA, iB = 1.f / lB;
    const size_t oA = (size_t)(b * T_SEQ + strip + r0) * C_DIM + h * HDIM;
    const size_t oB = oA + (size_t)8 * C_DIM;
    #pragma unroll
    for (int nj = 0; nj < 8; nj++) {
        const int col = nj * 8 + q2;
        uint32_t hA, lAa, hB, lBb;
        pack_hilo(o[nj][0] * iA, o[nj][1] * iA, hA, lAa);
        pack_hilo(o[nj][2] * iB, o[nj][3] * iB, hB, lBb);
        *(uint32_t*)(yh + oA + col) = hA;
        *(uint32_t*)(yl + oA + col) = lAa;
        *(uint32_t*)(yh + oB + col) = hB;
        *(uint32_t*)(yl + oB + col) = lBb;
    }
}

// ---------------------------------------------------------------------------
// Launch
// ---------------------------------------------------------------------------
extern "C" void kernel_launch(void* const* d_in, const int* in_sizes, int n_in,
                              void* d_out, int out_size)
{
    const float* x      = (const float*)d_in[0];
    const float* ln1_g  = (const float*)d_in[1];
    const float* ln1_b  = (const float*)d_in[2];
    const float* W_attn = (const float*)d_in[3];
    const float* b_attn = (const float*)d_in[4];
    const float* W_o    = (const float*)d_in[5];
    const float* b_o    = (const float*)d_in[6];
    const float* ln2_g  = (const float*)d_in[7];
    const float* ln2_b  = (const float*)d_in[8];
    const float* W_fc   = (const float*)d_in[9];
    const float* b_fc   = (const float*)d_in[10];
    const float* W_fc2  = (const float*)d_in[11];
    const float* b_fc2  = (const float*)d_in[12];
    float* out = (float*)d_out;

    __half *h_hi, *h_lo, *qkv_hi, *qkv_lo, *y_hi, *y_lo, *fc_hi, *fc_lo;
    __half *Wa, *Wo, *Wf, *W2;
    float *x1;
    cudaGetSymbolAddress((void**)&h_hi,   g_h_hi);
    cudaGetSymbolAddress((void**)&h_lo,   g_h_lo);
    cudaGetSymbolAddress((void**)&qkv_hi, g_qkv_hi);
    cudaGetSymbolAddress((void**)&qkv_lo, g_qkv_lo);
    cudaGetSymbolAddress((void**)&y_hi,   g_y_hi);
    cudaGetSymbolAddress((void**)&y_lo,   g_y_lo);
    cudaGetSymbolAddress((void**)&x1,     g_x1);
    cudaGetSymbolAddress((void**)&fc_hi,  g_fc_hi);
    cudaGetSymbolAddress((void**)&fc_lo,  g_fc_lo);
    cudaGetSymbolAddress((void**)&Wa,     g_Wa);
    cudaGetSymbolAddress((void**)&Wo,     g_Wo);
    cudaGetSymbolAddress((void**)&Wf,     g_Wf);
    cudaGetSymbolAddress((void**)&W2,     g_W2);

    cudaFuncSetAttribute(attn_tc,    cudaFuncAttributeMaxDynamicSharedMemorySize, AT_SMEM);
    cudaFuncSetAttribute(tc_gemm<0>, cudaFuncAttributeMaxDynamicSharedMemorySize, GM_SMEM);
    cudaFuncSetAttribute(tc_gemm<1>, cudaFuncAttributeMaxDynamicSharedMemorySize, GM_SMEM);
    cudaFuncSetAttribute(tc_gemm<2>, cudaFuncAttributeMaxDynamicSharedMemorySize, GM_SMEM);
    cudaFuncSetAttribute(tc_gemm<3>, cudaFuncAttributeMaxDynamicSharedMemorySize, GM_SMEM);

    // Weight prep (transpose to fp16, K-major)
    wconv_kernel<<<dim3(C3_DIM / 32, C_DIM / 32), 256>>>(W_attn, Wa, C_DIM, C3_DIM);
    wconv_kernel<<<dim3(C_DIM  / 32, C_DIM / 32), 256>>>(W_o,    Wo, C_DIM, C_DIM);
    wconv_kernel<<<dim3(C4_DIM / 32, C_DIM / 32), 256>>>(W_fc,   Wf, C_DIM, C4_DIM);
    wconv_kernel<<<dim3(C_DIM / 32, C4_DIM / 32), 256>>>(W_fc2,  W2, C4_DIM, C_DIM);

    // 1) LN1
    ln_kernel<<<M_TOK, 256>>>(x, ln1_g, ln1_b, h_hi, h_lo);
    // 2) QKV (split fp16 output)
    tc_gemm<3><<<dim3(C3_DIM / 128, M_TOK / 128), 256, GM_SMEM>>>(
        h_hi, h_lo, Wa, b_attn, nullptr, nullptr, qkv_hi, qkv_lo, C3_DIM, C_DIM);
    // 3) tensor-core flash attention
    attn_tc<<<dim3(T_SEQ / 128, N_HEAD, 2), 256, AT_SMEM>>>(qkv_hi, qkv_lo, y_hi, y_lo);
    // 4) x1 = x + y @ W_o + b_o
    tc_gemm<1><<<dim3(C_DIM / 128, M_TOK / 128), 256, GM_SMEM>>>(
        y_hi, y_lo, Wo, b_o, x, x1, nullptr, nullptr, C_DIM, C_DIM);
    // 5) LN2
    ln_kernel<<<M_TOK, 256>>>(x1, ln2_g, ln2_b, h_hi, h_lo);
    // 6) fc = gelu(h @ W_fc + b_fc)
    tc_gemm<2><<<dim3(C4_DIM / 128, M_TOK / 128), 256, GM_SMEM>>>(
        h_hi, h_lo, Wf, b_fc, nullptr, nullptr, fc_hi, fc_lo, C4_DIM, C_DIM);
    // 7) out = x1 + fc @ W_fc2 + b_fc2
    tc_gemm<1><<<dim3(C_DIM / 128, M_TOK / 128), 256, GM_SMEM>>>(
        fc_hi, fc_lo, W2, b_fc2, x1, out, nullptr, nullptr, C_DIM, C4_DIM);
}

// round 8
// speedup vs baseline: 8.5136x; 1.7116x over previous
#include <cuda_runtime.h>
#include <cuda_fp16.h>
#include <math.h>
#include <stdint.h>

#define M_TOK   4096
#define C_DIM   1024
#define C3_DIM  3072
#define C4_DIM  4096
#define N_HEAD  16
#define HDIM    64
#define T_SEQ   2048

// ---------------------------------------------------------------------------
// Scratch (device globals; no runtime allocation)
// ---------------------------------------------------------------------------
__device__ __half g_h  [M_TOK * C_DIM];
__device__ __half g_qkv[M_TOK * C3_DIM];
__device__ __half g_y  [M_TOK * C_DIM];
__device__ float  g_x1 [M_TOK * C_DIM];
__device__ __half g_fc [M_TOK * C4_DIM];
// Transposed fp16 weights: [N, K] K-major
__device__ __half g_Wa[C3_DIM * C_DIM];
__device__ __half g_Wo[C_DIM * C_DIM];
__device__ __half g_Wf[C4_DIM * C_DIM];
__device__ __half g_W2[C_DIM * C4_DIM];

// ---------------------------------------------------------------------------
// Helpers
// ---------------------------------------------------------------------------
__device__ __forceinline__ uint32_t sm_u32(const void* p) {
    uint32_t a;
    asm("{ .reg .u64 t; cvta.to.shared.u64 t, %1; cvt.u32.u64 %0, t; }"
        : "=r"(a) : "l"(p));
    return a;
}

__device__ __forceinline__ void cp16(uint32_t s, const void* g) {
    asm volatile("cp.async.cg.shared.global [%0], [%1], 16;"
                 :: "r"(s), "l"(g) : "memory");
}
#define CP_COMMIT() asm volatile("cp.async.commit_group;" ::: "memory")
#define CP_WAIT2()  asm volatile("cp.async.wait_group 2;" ::: "memory")
#define CP_WAIT1()  asm volatile("cp.async.wait_group 1;" ::: "memory")
#define CP_WAIT0()  asm volatile("cp.async.wait_group 0;" ::: "memory")

__device__ __forceinline__ void ldsm4(uint32_t* r, uint32_t a) {
    asm volatile("ldmatrix.sync.aligned.m8n8.x4.shared.b16 {%0,%1,%2,%3}, [%4];"
        : "=r"(r[0]), "=r"(r[1]), "=r"(r[2]), "=r"(r[3]) : "r"(a));
}
__device__ __forceinline__ void ldsm4t(uint32_t* r, uint32_t a) {
    asm volatile("ldmatrix.sync.aligned.m8n8.x4.trans.shared.b16 {%0,%1,%2,%3}, [%4];"
        : "=r"(r[0]), "=r"(r[1]), "=r"(r[2]), "=r"(r[3]) : "r"(a));
}

__device__ __forceinline__ void mma16816(float* d, const uint32_t* a,
                                         uint32_t b0, uint32_t b1) {
    asm volatile("mma.sync.aligned.m16n8k16.row.col.f32.f16.f16.f32 "
        "{%0,%1,%2,%3}, {%4,%5,%6,%7}, {%8,%9}, {%0,%1,%2,%3};"
        : "+f"(d[0]), "+f"(d[1]), "+f"(d[2]), "+f"(d[3])
        : "r"(a[0]), "r"(a[1]), "r"(a[2]), "r"(a[3]), "r"(b0), "r"(b1));
}

__device__ __forceinline__ float gelu_t(float x) {
    float x3 = x * x * x;
    float u = 0.7978845608028654f * (x + 0.044715f * x3);
    return 0.5f * x * (1.0f + tanhf(u));
}

__device__ __forceinline__ uint32_t pack2(float a, float b) {
    __half2 v = __floats2half2_rn(a, b);
    return *(uint32_t*)&v;
}

// ---------------------------------------------------------------------------
// Weight transpose to fp16: W[K,N] fp32 -> T[N,K] fp16
// ---------------------------------------------------------------------------
__global__ void __launch_bounds__(256) wconv_kernel(
    const float* __restrict__ W, __half* __restrict__ T, int K, int N)
{
    __shared__ float tile[32][33];
    const int n0 = blockIdx.x * 32, k0 = blockIdx.y * 32;
    const int tx = threadIdx.x & 31, ty = threadIdx.x >> 5;
    #pragma unroll
    for (int j = 0; j < 32; j += 8)
        tile[ty + j][tx] = W[(size_t)(k0 + ty + j) * N + n0 + tx];
    __syncthreads();
    #pragma unroll
    for (int j = 0; j < 32; j += 8)
        T[(size_t)(n0 + ty + j) * K + k0 + tx] = __float2half_rn(tile[tx][ty + j]);
}

// ---------------------------------------------------------------------------
// LayerNorm -> fp16 output
// ---------------------------------------------------------------------------
__global__ void __launch_bounds__(256) ln_kernel(
    const float* __restrict__ x, const float* __restrict__ g,
    const float* __restrict__ b, __half* __restrict__ oh)
{
    __shared__ float red_s[8], red_ss[8];
    const int row = blockIdx.x;
    const int t = threadIdx.x;
    const float* xr = x + (size_t)row * C_DIM;

    float4 v = *(const float4*)(xr + t * 4);
    float s  = v.x + v.y + v.z + v.w;
    float ss = v.x*v.x + v.y*v.y + v.z*v.z + v.w*v.w;
    #pragma unroll
    for (int o = 16; o; o >>= 1) {
        s  += __shfl_xor_sync(0xffffffffu, s,  o);
        ss += __shfl_xor_sync(0xffffffffu, ss, o);
    }
    if ((t & 31) == 0) { red_s[t >> 5] = s; red_ss[t >> 5] = ss; }
    __syncthreads();
    if (t < 32) {
        float a = (t < 8) ? red_s[t]  : 0.f;
        float c = (t < 8) ? red_ss[t] : 0.f;
        #pragma unroll
        for (int o = 4; o; o >>= 1) {
            a += __shfl_xor_sync(0xffffffffu, a, o);
            c += __shfl_xor_sync(0xffffffffu, c, o);
        }
        if (t == 0) { red_s[0] = a; red_ss[0] = c; }
    }
    __syncthreads();
    const float mu  = red_s[0]  * (1.0f / C_DIM);
    const float var = red_ss[0] * (1.0f / C_DIM) - mu * mu;
    const float inv = rsqrtf(var + 1e-5f);

    float4 gv = *(const float4*)(g + t * 4);
    float4 bv = *(const float4*)(b + t * 4);
    float o0 = (v.x - mu) * inv * gv.x + bv.x;
    float o1 = (v.y - mu) * inv * gv.y + bv.y;
    float o2 = (v.z - mu) * inv * gv.z + bv.z;
    float o3 = (v.w - mu) * inv * gv.w + bv.w;

    size_t base = (size_t)row * C_DIM + t * 4;
    *(uint32_t*)(oh + base)     = pack2(o0, o1);
    *(uint32_t*)(oh + base + 2) = pack2(o2, o3);
}

// ---------------------------------------------------------------------------
// mma.sync fp16 GEMM: C = A @ B^T (+bias [+res] [gelu] [fp16-out])
// CTA 128x128x32, 8 warps (2x4), warp tile 64x32.
// 4-stage cp.async pipeline, ONE __syncthreads per K-chunk.
// MODE 0: Cf = d + bias
// MODE 1: Cf = d + bias + res
// MODE 2: Ch = fp16(gelu(d + bias))
// MODE 3: Ch = fp16(d + bias)
// ---------------------------------------------------------------------------
#define TILE_B   10240                // 128 rows x 80 bytes
#define STAGE_B  (2 * TILE_B)         // A, B = 20480
#define GM_SMEM  (4 * STAGE_B)        // 4 stages = 81920

template<int MODE>
__global__ void __launch_bounds__(256, 2) tc_gemm(
    const __half* __restrict__ A, const __half* __restrict__ B,
    const float* __restrict__ bias, const float* __restrict__ res,
    float* __restrict__ Cf, __half* __restrict__ Ch,
    int N, int K)
{
    extern __shared__ char smem[];
    const uint32_t sb = sm_u32(smem);
    const int t = threadIdx.x, w = t >> 5, lane = t & 31;
    const int wm = w >> 2, wn = w & 3;
    const int bn0 = blockIdx.x * 128, bm0 = blockIdx.y * 128;
    const int NC = K >> 5;

    const char* gpA = (const char*)(A + (size_t)bm0 * K);
    const char* gpB = (const char*)(B + (size_t)bn0 * K);
    const size_t ldb = (size_t)K * 2;

    const int c16 = t & 3, lr = t >> 2;

    auto load_chunk = [&](int i) {
        const int k0 = i << 5;
        const uint32_t st = sb + (i & 3) * STAGE_B;
        #pragma unroll
        for (int half = 0; half < 2; half++) {
            const int r = lr + half * 64;
            const size_t go = (size_t)r * ldb + (size_t)k0 * 2 + c16 * 16;
            cp16(st + r * 80 + c16 * 16,          gpA + go);
            cp16(st + TILE_B + r * 80 + c16 * 16, gpB + go);
        }
    };

    const uint32_t a_off = (uint32_t)(lane & 15) * 80 + (uint32_t)(lane >> 4) * 16;
    const uint32_t b_off = (uint32_t)((lane >> 4) * 8 + (lane & 7)) * 80
                         + (uint32_t)((lane >> 3) & 1) * 16;

    float acc[4][4][4];
    #pragma unroll
    for (int i = 0; i < 4; i++)
        #pragma unroll
        for (int j = 0; j < 4; j++)
            #pragma unroll
            for (int k = 0; k < 4; k++) acc[i][j][k] = 0.f;

    load_chunk(0); CP_COMMIT();
    load_chunk(1); CP_COMMIT();
    load_chunk(2); CP_COMMIT();

    for (int i = 0; i < NC; i++) {
        const int rem = NC - 1 - i;
        if (rem >= 2)      { CP_WAIT2(); }
        else if (rem == 1) { CP_WAIT1(); }
        else               { CP_WAIT0(); }
        __syncthreads();
        if (i + 3 < NC) { load_chunk(i + 3); CP_COMMIT(); }

        const uint32_t st = sb + (i & 3) * STAGE_B;
        #pragma unroll
        for (int ks = 0; ks < 2; ks++) {
            const uint32_t kb = ks * 32;
            uint32_t bh[2][4];
            #pragma unroll
            for (int g = 0; g < 2; g++) {
                uint32_t nb = (uint32_t)(wn * 32 + g * 16) * 80 + kb + b_off;
                ldsm4(bh[g], st + TILE_B + nb);
            }
            #pragma unroll
            for (int mi = 0; mi < 4; mi++) {
                uint32_t mb = (uint32_t)(wm * 64 + mi * 16) * 80 + kb + a_off;
                uint32_t ah[4];
                ldsm4(ah, st + mb);
                #pragma unroll
                for (int nj = 0; nj < 4; nj++) {
                    const int g = nj >> 1, h2 = (nj & 1) * 2;
                    mma16816(acc[mi][nj], ah, bh[g][h2], bh[g][h2 + 1]);
                }
            }
        }
    }

    const int rr = lane >> 2, cc = (lane & 3) * 2;
    #pragma unroll
    for (int mi = 0; mi < 4; mi++) {
        #pragma unroll
        for (int nj = 0; nj < 4; nj++) {
            const int r0 = bm0 + wm * 64 + mi * 16 + rr;
            const int c0 = bn0 + wn * 32 + nj * 8 + cc;
            const float2 b2 = *(const float2*)(bias + c0);
            float v00 = acc[mi][nj][0] + b2.x;
            float v01 = acc[mi][nj][1] + b2.y;
            float v10 = acc[mi][nj][2] + b2.x;
            float v11 = acc[mi][nj][3] + b2.y;
            if (MODE == 1) {
                const float2 r2a = *(const float2*)(res + (size_t)r0 * N + c0);
                const float2 r2b = *(const float2*)(res + (size_t)(r0 + 8) * N + c0);
                v00 += r2a.x; v01 += r2a.y; v10 += r2b.x; v11 += r2b.y;
            }
            if (MODE >= 2) {
                if (MODE == 2) {
                    v00 = gelu_t(v00); v01 = gelu_t(v01);
                    v10 = gelu_t(v10); v11 = gelu_t(v11);
                }
                *(uint32_t*)(Ch + (size_t)r0 * N + c0)       = pack2(v00, v01);
                *(uint32_t*)(Ch + (size_t)(r0 + 8) * N + c0) = pack2(v10, v11);
            } else {
                *(float2*)(Cf + (size_t)r0 * N + c0)       = make_float2(v00, v01);
                *(float2*)(Cf + (size_t)(r0 + 8) * N + c0) = make_float2(v10, v11);
            }
        }
    }
}

// ---------------------------------------------------------------------------
// Tensor-core causal flash attention (pure fp16 inputs, fp32 accum).
// Grid (T/128, H, B), 256 threads (8 warps x 16 q-rows). KV tile 64.
// ---------------------------------------------------------------------------
#define AT_TILE  9216                    // 64 rows x 144B
#define AT_STAGE (2 * AT_TILE)           // K, V
#define AT_SMEM  (2 * AT_STAGE)          // 36864

__global__ void __launch_bounds__(256) attn_tc(
    const __half* __restrict__ qv, __half* __restrict__ y)
{
    extern __shared__ char smem[];
    const uint32_t sb = sm_u32(smem);
    const int qt = blockIdx.x, h = blockIdx.y, b = blockIdx.z;
    const int t = threadIdx.x, lane = t & 31;
    const int strip = qt * 128 + (t >> 5) * 16;
    const int r0 = lane >> 2, q2 = (lane & 3) << 1;

    const size_t base2 = (size_t)(b * T_SEQ) * C3_DIM + h * HDIM;

    uint32_t Qh[4][4];
    {
        const size_t ra = base2 + (size_t)(strip + r0) * C3_DIM;
        const size_t rb = ra + (size_t)8 * C3_DIM;
        #pragma unroll
        for (int kt = 0; kt < 4; kt++) {
            const int c0 = kt * 16 + q2;
            Qh[kt][0] = *(const uint32_t*)(qv + ra + c0);
            Qh[kt][1] = *(const uint32_t*)(qv + rb + c0);
            Qh[kt][2] = *(const uint32_t*)(qv + ra + c0 + 8);
            Qh[kt][3] = *(const uint32_t*)(qv + rb + c0 + 8);
        }
    }

    float o[8][4];
    #pragma unroll
    for (int i = 0; i < 8; i++)
        #pragma unroll
        for (int e = 0; e < 4; e++) o[i][e] = 0.f;
    float mA = -1e30f, mB = -1e30f, lA = 0.f, lB = 0.f;
    const int jmax = 2 * qt + 1;

    auto load_kv = [&](int j) {
        const uint32_t st = sb + (j & 1) * AT_STAGE;
        #pragma unroll
        for (int i = 0; i < 2; i++) {
            const int id = t + 256 * i;
            const int row = id >> 3, c = id & 7;
            const size_t src = base2 + (size_t)(j * 64 + row) * C3_DIM + c * 8;
            const uint32_t dst = st + row * 144 + c * 16;
            cp16(dst,           qv + src + C_DIM);       // K
            cp16(dst + AT_TILE, qv + src + 2 * C_DIM);   // V
        }
    };

    load_kv(0); CP_COMMIT();

    for (int j = 0; j <= jmax; j++) {
        if (j < jmax) {
            load_kv(j + 1); CP_COMMIT();
            CP_WAIT1();
        } else {
            CP_WAIT0();
        }
        __syncthreads();

        const int jb = j * 64;
        if (jb <= strip + 15) {
            const uint32_t st = sb + (j & 1) * AT_STAGE;
            float s[8][4];
            #pragma unroll
            for (int i = 0; i < 8; i++)
                #pragma unroll
                for (int e = 0; e < 4; e++) s[i][e] = 0.f;

            // ---- S = Q K^T ----
            const uint32_t koffb = st + ((lane >> 4) * 8 + (lane & 7)) * 144
                                 + ((lane >> 3) & 1) * 16;
            #pragma unroll
            for (int kt = 0; kt < 4; kt++) {
                #pragma unroll
                for (int g = 0; g < 4; g++) {
                    const uint32_t off = koffb + g * (16 * 144) + kt * 32;
                    uint32_t kh4[4];
                    ldsm4(kh4, off);
                    mma16816(s[2*g],   Qh[kt], kh4[0], kh4[1]);
                    mma16816(s[2*g+1], Qh[kt], kh4[2], kh4[3]);
                }
            }

            // ---- softmax (online) ----
            const bool domask = (jb + 63 > strip);
            const int rowA = strip + r0, rowB = rowA + 8;
            float mtA = -1e30f, mtB = -1e30f;
            #pragma unroll
            for (int nj = 0; nj < 8; nj++) {
                #pragma unroll
                for (int e = 0; e < 4; e++) s[nj][e] *= 0.125f;
                if (domask) {
                    const int col0 = jb + nj * 8 + q2;
                    if (col0     > rowA) s[nj][0] = -1e30f;
                    if (col0 + 1 > rowA) s[nj][1] = -1e30f;
                    if (col0     > rowB) s[nj][2] = -1e30f;
                    if (col0 + 1 > rowB) s[nj][3] = -1e30f;
                }
                mtA = fmaxf(mtA, fmaxf(s[nj][0], s[nj][1]));
                mtB = fmaxf(mtB, fmaxf(s[nj][2], s[nj][3]));
            }
            mtA = fmaxf(mtA, __shfl_xor_sync(0xffffffffu, mtA, 1));
            mtA = fmaxf(mtA, __shfl_xor_sync(0xffffffffu, mtA, 2));
            mtB = fmaxf(mtB, __shfl_xor_sync(0xffffffffu, mtB, 1));
            mtB = fmaxf(mtB, __shfl_xor_sync(0xffffffffu, mtB, 2));
            const float mnA = fmaxf(mA, mtA), mnB = fmaxf(mB, mtB);
            const float aA = __expf(mA - mnA), aB = __expf(mB - mnB);

            float sA = 0.f, sB = 0.f;
            uint32_t ph[4][4];
            #pragma unroll
            for (int g = 0; g < 4; g++) {
                float p00 = __expf(s[2*g][0]   - mnA), p01 = __expf(s[2*g][1]   - mnA);
                float p10 = __expf(s[2*g][2]   - mnB), p11 = __expf(s[2*g][3]   - mnB);
                float p20 = __expf(s[2*g+1][0] - mnA), p21 = __expf(s[2*g+1][1] - mnA);
                float p30 = __expf(s[2*g+1][2] - mnB), p31 = __expf(s[2*g+1][3] - mnB);
                sA += p00 + p01 + p20 + p21;
                sB += p10 + p11 + p30 + p31;
                ph[g][0] = pack2(p00, p01);
                ph[g][1] = pack2(p10, p11);
                ph[g][2] = pack2(p20, p21);
                ph[g][3] = pack2(p30, p31);
            }
            sA += __shfl_xor_sync(0xffffffffu, sA, 1);
            sA += __shfl_xor_sync(0xffffffffu, sA, 2);
            sB += __shfl_xor_sync(0xffffffffu, sB, 1);
            sB += __shfl_xor_sync(0xffffffffu, sB, 2);
            lA = lA * aA + sA;
            lB = lB * aB + sB;
            mA = mnA; mB = mnB;
            #pragma unroll
            for (int nj = 0; nj < 8; nj++) {
                o[nj][0] *= aA; o[nj][1] *= aA;
                o[nj][2] *= aB; o[nj][3] *= aB;
            }

            // ---- O += P V ----
            const uint32_t voffb = st + AT_TILE + (lane & 15) * 144
                                 + (lane >> 4) * 16;
            #pragma unroll
            for (int g = 0; g < 4; g++) {
                #pragma unroll
                for (int nh = 0; nh < 4; nh++) {
                    const uint32_t off = voffb + g * (16 * 144) + nh * 32;
                    uint32_t vh4[4];
                    ldsm4t(vh4, off);
                    mma16816(o[2*nh],   ph[g], vh4[0], vh4[1]);
                    mma16816(o[2*nh+1], ph[g], vh4[2], vh4[3]);
                }
            }
        }
        __syncthreads();
    }

    const float iA = 1.f / lA, iB = 1.f / lB;
    const size_t oA = (size_t)(b * T_SEQ + strip + r0) * C_DIM + h * HDIM;
    const size_t oB = oA + (size_t)8 * C_DIM;
    #pragma unroll
    for (int nj = 0; nj < 8; nj++) {
        const int col = nj * 8 + q2;
        *(uint32_t*)(y + oA + col) = pack2(o[nj][0] * iA, o[nj][1] * iA);
        *(uint32_t*)(y + oB + col) = pack2(o[nj][2] * iB, o[nj][3] * iB);
    }
}

// ---------------------------------------------------------------------------
// Launch
// ---------------------------------------------------------------------------
extern "C" void kernel_launch(void* const* d_in, const int* in_sizes, int n_in,
                              void* d_out, int out_size)
{
    const float* x      = (const float*)d_in[0];
    const float* ln1_g  = (const float*)d_in[1];
    const float* ln1_b  = (const float*)d_in[2];
    const float* W_attn = (const float*)d_in[3];
    const float* b_attn = (const float*)d_in[4];
    const float* W_o    = (const float*)d_in[5];
    const float* b_o    = (const float*)d_in[6];
    const float* ln2_g  = (const float*)d_in[7];
    const float* ln2_b  = (const float*)d_in[8];
    const float* W_fc   = (const float*)d_in[9];
    const float* b_fc   = (const float*)d_in[10];
    const float* W_fc2  = (const float*)d_in[11];
    const float* b_fc2  = (const float*)d_in[12];
    float* out = (float*)d_out;

    __half *h, *qkv, *y, *fc, *Wa, *Wo, *Wf, *W2;
    float *x1;
    cudaGetSymbolAddress((void**)&h,   g_h);
    cudaGetSymbolAddress((void**)&qkv, g_qkv);
    cudaGetSymbolAddress((void**)&y,   g_y);
    cudaGetSymbolAddress((void**)&x1,  g_x1);
    cudaGetSymbolAddress((void**)&fc,  g_fc);
    cudaGetSymbolAddress((void**)&Wa,  g_Wa);
    cudaGetSymbolAddress((void**)&Wo,  g_Wo);
    cudaGetSymbolAddress((void**)&Wf,  g_Wf);
    cudaGetSymbolAddress((void**)&W2,  g_W2);

    cudaFuncSetAttribute(attn_tc,    cudaFuncAttributeMaxDynamicSharedMemorySize, AT_SMEM);
    cudaFuncSetAttribute(tc_gemm<0>, cudaFuncAttributeMaxDynamicSharedMemorySize, GM_SMEM);
    cudaFuncSetAttribute(tc_gemm<1>, cudaFuncAttributeMaxDynamicSharedMemorySize, GM_SMEM);
    cudaFuncSetAttribute(tc_gemm<2>, cudaFuncAttributeMaxDynamicSharedMemorySize, GM_SMEM);
    cudaFuncSetAttribute(tc_gemm<3>, cudaFuncAttributeMaxDynamicSharedMemorySize, GM_SMEM);

    // Weight prep (transpose to fp16, K-major)
    wconv_kernel<<<dim3(C3_DIM / 32, C_DIM / 32), 256>>>(W_attn, Wa, C_DIM, C3_DIM);
    wconv_kernel<<<dim3(C_DIM  / 32, C_DIM / 32), 256>>>(W_o,    Wo, C_DIM, C_DIM);
    wconv_kernel<<<dim3(C4_DIM / 32, C_DIM / 32), 256>>>(W_fc,   Wf, C_DIM, C4_DIM);
    wconv_kernel<<<dim3(C_DIM / 32, C4_DIM / 32), 256>>>(W_fc2,  W2, C4_DIM, C_DIM);

    // 1) LN1
    ln_kernel<<<M_TOK, 256>>>(x, ln1_g, ln1_b, h);
    // 2) QKV (fp16 output)
    tc_gemm<3><<<dim3(C3_DIM / 128, M_TOK / 128), 256, GM_SMEM>>>(
        h, Wa, b_attn, nullptr, nullptr, qkv, C3_DIM, C_DIM);
    // 3) tensor-core flash attention
    attn_tc<<<dim3(T_SEQ / 128, N_HEAD, 2), 256, AT_SMEM>>>(qkv, y);
    // 4) x1 = x + y @ W_o + b_o
    tc_gemm<1><<<dim3(C_DIM / 128, M_TOK / 128), 256, GM_SMEM>>>(
        y, Wo, b_o, x, x1, nullptr, C_DIM, C_DIM);
    // 5) LN2
    ln_kernel<<<M_TOK, 256>>>(x1, ln2_g, ln2_b, h);
    // 6) fc = gelu(h @ W_fc + b_fc)
    tc_gemm<2><<<dim3(C4_DIM / 128, M_TOK / 128), 256, GM_SMEM>>>(
        h, Wf, b_fc, nullptr, nullptr, fc, C4_DIM, C_DIM);
    // 7) out = x1 + fc @ W_fc2 + b_fc2
    tc_gemm<1><<<dim3(C_DIM / 128, M_TOK / 128), 256, GM_SMEM>>>(
        fc, W2, b_fc2, x1, out, nullptr, C_DIM, C4_DIM);
}